// round 7
// baseline (speedup 1.0000x reference)
#include <cuda_runtime.h>
#include <cuda_bf16.h>
#include <cstdint>

#define D 128
#define NW 100000
#define NT 10000
#define ND 50000
#define NV (NW + NT + NT + ND + ND)   // 220000 virtual (relation,dst) nodes
#define NROW (NW + NT + ND)           // 160000 output rows
#define SCAN_BLK 54                   // ceil(NV/4096)
#define TILES_W 782                   // ceil(NW/128)
#define TILES_T 79                    // ceil(NT/128)

// ---------------- scratch (device globals: allocation-free) ----------------
__device__ float g_h[(size_t)(NW + NT) * D];  // unified composed features (word|topic)
__device__ int   g_cnt[NV];
__device__ int   g_offs[NV];
__device__ int   g_cursor[NV];
__device__ float g_rcnt[NV];
__device__ int   g_bsum[SCAN_BLK];
__device__ int2  g_perm[600000];
__device__ float g_T1[D * (D + 1)];
__device__ float g_bw[D];
__device__ float g_bt[D];
// composed B, bf16 split, plain [n][k] row-major (n = output dim, k = input dim)
__device__ __nv_bfloat16 g_Bwh[D * D];
__device__ __nv_bfloat16 g_Bwl[D * D];
__device__ __nv_bfloat16 g_Bth[D * D];
__device__ __nv_bfloat16 g_Btl[D * D];

// ---------------- mma/ldmatrix helpers (plain PTX, sm_80+) ----------------
__device__ __forceinline__ uint32_t smem_u32(const void* p) {
    uint32_t a;
    asm("{ .reg .u64 t; cvta.to.shared.u64 t, %1; cvt.u32.u64 %0, t; }" : "=r"(a) : "l"(p));
    return a;
}
__device__ __forceinline__ void ldmx4(uint32_t* r, uint32_t addr) {
    asm volatile("ldmatrix.sync.aligned.m8n8.x4.shared.b16 {%0,%1,%2,%3}, [%4];"
                 : "=r"(r[0]), "=r"(r[1]), "=r"(r[2]), "=r"(r[3]) : "r"(addr));
}
#define MMA_BF16(c0, c1, c2, c3, a0, a1, a2, a3, b0, b1)                        \
    asm volatile(                                                               \
        "mma.sync.aligned.m16n8k16.row.col.f32.bf16.bf16.f32 "                  \
        "{%0,%1,%2,%3}, {%4,%5,%6,%7}, {%8,%9}, {%0,%1,%2,%3};"                 \
        : "+f"(c0), "+f"(c1), "+f"(c2), "+f"(c3)                                \
        : "r"(a0), "r"(a1), "r"(a2), "r"(a3), "r"(b0), "r"(b1))

// ---------------- weight composition ----------------
__global__ void __launch_bounds__(128) compose1(
    const float* __restrict__ Www, const float* __restrict__ Wwt,
    const float* __restrict__ bww, const float* __restrict__ bwt,
    const float* __restrict__ Wtd, const float* __restrict__ Wtt,
    const float* __restrict__ btd, const float* __restrict__ btt) {
    extern __shared__ float sm[];
    float* Ws = sm;
    float* Av = sm + 128 * 129;
    const int b = blockIdx.x;
    const int tid = threadIdx.x;
    const float* Wstage = (b < 129) ? Wwt : Wtt;
#pragma unroll 8
    for (int i = 0; i < 128; i++) Ws[i * 129 + tid] = Wstage[i * 128 + tid];
    if (b < 128)        Av[tid] = Www[tid * 128 + b];
    else if (b == 128)  Av[tid] = bww[tid];
    else if (b < 257)   Av[tid] = Wtd[tid * 128 + (b - 129)];
    else                Av[tid] = btd[tid];
    __syncthreads();
    float s = 0.f;
#pragma unroll 16
    for (int k = 0; k < 128; k++) s += Av[k] * Ws[tid * 129 + k];
    if (b < 128)        g_T1[b * 128 + tid] = s;
    else if (b == 128)  g_T1[128 * 128 + tid] = s + bwt[tid];
    else if (b < 257) {
        int k = b - 129;                  // n = tid, k = input dim
        __nv_bfloat16 hh = __float2bfloat16(s);
        g_Bth[tid * 128 + k] = hh;
        g_Btl[tid * 128 + k] = __float2bfloat16(s - __bfloat162float(hh));
    } else              g_bt[tid] = s + btt[tid];
}
__global__ void __launch_bounds__(128) compose2(
    const float* __restrict__ Wwd, const float* __restrict__ bwd) {
    extern __shared__ float sm[];
    float* Ws = sm;
    float* Av = sm + 128 * 129;
    const int b = blockIdx.x;
    const int tid = threadIdx.x;
#pragma unroll 8
    for (int i = 0; i < 128; i++) Ws[i * 129 + tid] = Wwd[i * 128 + tid];
    Av[tid] = g_T1[b * 128 + tid];
    __syncthreads();
    float s = 0.f;
#pragma unroll 16
    for (int k = 0; k < 128; k++) s += Av[k] * Ws[tid * 129 + k];
    if (b < 128) {
        __nv_bfloat16 hh = __float2bfloat16(s);
        g_Bwh[tid * 128 + b] = hh;
        g_Bwl[tid * 128 + b] = __float2bfloat16(s - __bfloat162float(hh));
    } else g_bw[tid] = s + bwd[tid];
}

// ---------------- tensor-core GEMM: H[M,128] = A @ Bcomp^T + bias --------------
__global__ void __launch_bounds__(256, 1)
gemm_mma(const float* __restrict__ Aw, const float* __restrict__ At,
         float* __restrict__ H) {
    extern __shared__ __align__(16) char smem[];
    __nv_bfloat16* As_hi = (__nv_bfloat16*)smem;                 // [128][136]
    __nv_bfloat16* As_lo = (__nv_bfloat16*)(smem + 34816);
    __nv_bfloat16* Bs_hi = (__nv_bfloat16*)(smem + 69632);
    __nv_bfloat16* Bs_lo = (__nv_bfloat16*)(smem + 104448);
    const int tid = threadIdx.x;
    const int wid = tid >> 5, lane = tid & 31;

    const float* A;
    const __nv_bfloat16 *Bh, *Bl;
    const float* bias;
    float* C;
    int M, row0;
    if (blockIdx.x < TILES_W) {
        A = Aw; Bh = g_Bwh; Bl = g_Bwl; bias = g_bw; C = H;
        M = NW; row0 = blockIdx.x * 128;
    } else {
        A = At; Bh = g_Bth; Bl = g_Btl; bias = g_bt; C = H + (size_t)NW * D;
        M = NT; row0 = (blockIdx.x - TILES_W) * 128;
    }

    {
        const uint32_t* bh = (const uint32_t*)Bh;
        const uint32_t* bl = (const uint32_t*)Bl;
        uint32_t* dh = (uint32_t*)Bs_hi;
        uint32_t* dl = (uint32_t*)Bs_lo;
#pragma unroll
        for (int i = 0; i < 32; i++) {
            int idx = tid + 256 * i;
            int n = idx >> 6, w = idx & 63;
            dh[n * 68 + w] = __ldg(bh + idx);
            dl[n * 68 + w] = __ldg(bl + idx);
        }
    }
    {
#pragma unroll
        for (int i = 0; i < 16; i++) {
            int idx = tid + 256 * i;
            int r = idx >> 5, c4 = idx & 31;
            float4 f = (row0 + r < M)
                ? __ldg((const float4*)(A + (size_t)(row0 + r) * D) + c4)
                : make_float4(0.f, 0.f, 0.f, 0.f);
            __nv_bfloat16 h0 = __float2bfloat16(f.x), h1 = __float2bfloat16(f.y);
            __nv_bfloat16 h2 = __float2bfloat16(f.z), h3 = __float2bfloat16(f.w);
            __nv_bfloat162 ph0, ph1, pl0, pl1;
            ph0.x = h0; ph0.y = h1; ph1.x = h2; ph1.y = h3;
            pl0.x = __float2bfloat16(f.x - __bfloat162float(h0));
            pl0.y = __float2bfloat16(f.y - __bfloat162float(h1));
            pl1.x = __float2bfloat16(f.z - __bfloat162float(h2));
            pl1.y = __float2bfloat16(f.w - __bfloat162float(h3));
            int base = r * 136 + c4 * 4;
            *(__nv_bfloat162*)(As_hi + base)     = ph0;
            *(__nv_bfloat162*)(As_hi + base + 2) = ph1;
            *(__nv_bfloat162*)(As_lo + base)     = pl0;
            *(__nv_bfloat162*)(As_lo + base + 2) = pl1;
        }
    }
    __syncthreads();

    const uint32_t as_hi_b = smem_u32(As_hi), as_lo_b = smem_u32(As_lo);
    const uint32_t bs_hi_b = smem_u32(Bs_hi), bs_lo_b = smem_u32(Bs_lo);
    const int lr = lane & 7, lm = lane >> 3;

    uint32_t ah[8][4], al[8][4];
    {
        uint32_t arow = (uint32_t)(wid * 16 + lr + (lm & 1) * 8);
        uint32_t acol = (uint32_t)((lm >> 1) * 8);
        uint32_t abase = (arow * 136 + acol) * 2;
#pragma unroll
        for (int ks = 0; ks < 8; ks++) {
            ldmx4(ah[ks], as_hi_b + abase + ks * 32);
            ldmx4(al[ks], as_lo_b + abase + ks * 32);
        }
    }

    const int g = lane >> 2, t = lane & 3;
    const int orow0 = row0 + wid * 16 + g;
    const uint32_t bbase_sel = (lm >= 2) ? bs_lo_b : bs_hi_b;
    const uint32_t bcol = (uint32_t)((lm & 1) * 8);

#pragma unroll 4
    for (int nt = 0; nt < 16; nt++) {
        float c0 = 0.f, c1 = 0.f, c2 = 0.f, c3 = 0.f;
        uint32_t baddr = bbase_sel + (((uint32_t)(nt * 8 + lr)) * 136 + bcol) * 2;
#pragma unroll
        for (int ks = 0; ks < 8; ks++) {
            uint32_t b[4];
            ldmx4(b, baddr + ks * 32);
            MMA_BF16(c0, c1, c2, c3, ah[ks][0], ah[ks][1], ah[ks][2], ah[ks][3], b[0], b[1]);
            MMA_BF16(c0, c1, c2, c3, al[ks][0], al[ks][1], al[ks][2], al[ks][3], b[0], b[1]);
            MMA_BF16(c0, c1, c2, c3, ah[ks][0], ah[ks][1], ah[ks][2], ah[ks][3], b[2], b[3]);
        }
        int col = nt * 8 + t * 2;
        float2 b2 = __ldg((const float2*)(bias + col));
        if (orow0 < M)
            *(float2*)(C + (size_t)orow0 * D + col) = make_float2(c0 + b2.x, c1 + b2.y);
        if (orow0 + 8 < M)
            *(float2*)(C + (size_t)(orow0 + 8) * D + col) = make_float2(c2 + b2.x, c3 + b2.y);
    }
}

// ---------------- counts (int4 vectorized, fire-and-forget) ----------------
struct Cnt4Args {
    const int4* dst4[5];
    int vbase[5];
    int cum4[6];
};
__global__ void count_all(Cnt4Args a, int* __restrict__ cnt) {
    int g = blockIdx.x * blockDim.x + threadIdx.x;
    if (g >= a.cum4[5]) return;
    int r = 0;
    while (g >= a.cum4[r + 1]) r++;
    int4 d = __ldcs(a.dst4[r] + (g - a.cum4[r]));
    int* base = cnt + a.vbase[r];
    atomicAdd(base + d.x, 1);
    atomicAdd(base + d.y, 1);
    atomicAdd(base + d.z, 1);
    atomicAdd(base + d.w, 1);
}

// ---------------- scan pass A: per-block exclusive scan + rcnt --------------
__global__ void __launch_bounds__(1024) scanA(const int* __restrict__ cnt, int n,
                                              int* __restrict__ offs,
                                              float* __restrict__ rcnt,
                                              int* __restrict__ bsum) {
    __shared__ int wsum[32];
    const int tid = threadIdx.x;
    const int base = blockIdx.x * 4096 + tid * 4;
    int v[4];
#pragma unroll
    for (int k = 0; k < 4; k++) v[k] = (base + k < n) ? cnt[base + k] : 0;
#pragma unroll
    for (int k = 0; k < 4; k++)
        if (base + k < n) rcnt[base + k] = 1.0f / (float)max(v[k], 1);
    int t = v[0] + v[1] + v[2] + v[3];
    const int lane = tid & 31, w = tid >> 5;
    int inc = t;
#pragma unroll
    for (int dlt = 1; dlt < 32; dlt <<= 1) {
        int x = __shfl_up_sync(0xffffffffu, inc, dlt);
        if (lane >= dlt) inc += x;
    }
    if (lane == 31) wsum[w] = inc;
    __syncthreads();
    if (w == 0) {
        int si = wsum[lane];
#pragma unroll
        for (int dlt = 1; dlt < 32; dlt <<= 1) {
            int x = __shfl_up_sync(0xffffffffu, si, dlt);
            if (lane >= dlt) si += x;
        }
        wsum[lane] = si;
    }
    __syncthreads();
    int o = inc - t + (w > 0 ? wsum[w - 1] : 0);
#pragma unroll
    for (int k = 0; k < 4; k++) {
        if (base + k < n) offs[base + k] = o;
        o += v[k];
    }
    if (tid == 0) bsum[blockIdx.x] = wsum[31];
}

// ---------------- scan pass C (merged B): add block-prefix, init cursors ----
__global__ void __launch_bounds__(1024) scanC(int* __restrict__ offs, int n,
                                              const int* __restrict__ bsum,
                                              int* __restrict__ cursor) {
    __shared__ int pref;
    const int tid = threadIdx.x;
    if (tid < 32) {
        int acc = 0;
        for (int i = tid; i < blockIdx.x; i += 32) acc += bsum[i];
#pragma unroll
        for (int dlt = 16; dlt > 0; dlt >>= 1)
            acc += __shfl_down_sync(0xffffffffu, acc, dlt);
        if (tid == 0) pref = acc;
    }
    __syncthreads();
    const int add = pref;
    int base = blockIdx.x * 4096 + tid * 4;
#pragma unroll
    for (int k = 0; k < 4; k++) {
        int i = base + k;
        if (i < n) {
            int o = offs[i] + add;
            offs[i] = o;
            cursor[i] = o;
        }
    }
}

// ---------------- CSR fill (4 edges/thread, vectorized) ----------------
struct Fill4Args {
    const int4*   src4[5];
    const int4*   dst4[5];
    const float4* ew4[5];
    int vbase[5];
    int soff[5];
    int cum4[6];
};
__global__ void fill_kernel(Fill4Args a, const float* __restrict__ rcnt,
                            int* __restrict__ cursor, int2* __restrict__ perm) {
    int g = blockIdx.x * blockDim.x + threadIdx.x;
    if (g >= a.cum4[5]) return;
    int r = 0;
    while (g >= a.cum4[r + 1]) r++;
    int e4 = g - a.cum4[r];
    int4   s = __ldcs(a.src4[r] + e4);
    int4   d = __ldcs(a.dst4[r] + e4);
    float4 w = __ldcs(a.ew4[r] + e4);
    const int vb = a.vbase[r], so = a.soff[r];
    {
        int v = vb + d.x;
        int pos = atomicAdd(cursor + v, 1);
        perm[pos] = make_int2(s.x + so, __float_as_int(w.x * __ldg(rcnt + v)));
    }
    {
        int v = vb + d.y;
        int pos = atomicAdd(cursor + v, 1);
        perm[pos] = make_int2(s.y + so, __float_as_int(w.y * __ldg(rcnt + v)));
    }
    {
        int v = vb + d.z;
        int pos = atomicAdd(cursor + v, 1);
        perm[pos] = make_int2(s.z + so, __float_as_int(w.z * __ldg(rcnt + v)));
    }
    {
        int v = vb + d.w;
        int pos = atomicAdd(cursor + v, 1);
        perm[pos] = make_int2(s.w + so, __float_as_int(w.w * __ldg(rcnt + v)));
    }
}

// ---------------- gather: one warp per output row, fused relu ---------------
__device__ __forceinline__ void edge_fma(float4& acc, int sidx, float c,
                                         const float* __restrict__ H, int lane) {
    float4 h = __ldg((const float4*)(H + (size_t)sidx * D) + lane);
    acc.x = fmaf(c, h.x, acc.x);
    acc.y = fmaf(c, h.y, acc.y);
    acc.z = fmaf(c, h.z, acc.z);
    acc.w = fmaf(c, h.w, acc.w);
}
__global__ void __launch_bounds__(256) gather_kernel(
    const int2* __restrict__ perm, const int* __restrict__ offs,
    const int* __restrict__ cnt, const float* __restrict__ H,
    float* __restrict__ out) {
    int gid = blockIdx.x * 256 + threadIdx.x;
    int row = gid >> 5;
    if (row >= NROW) return;
    int lane = gid & 31;

    int v0, v1;
    if (row < NW) { v0 = row; v1 = -1; }
    else if (row < NW + NT) { int t = row - NW; v0 = NW + t; v1 = NW + NT + t; }
    else { int d = row - NW - NT; v0 = NW + 2 * NT + d; v1 = NW + 2 * NT + ND + d; }

    float4 acc = make_float4(0.f, 0.f, 0.f, 0.f);
#pragma unroll
    for (int pass = 0; pass < 2; pass++) {
        int v = pass ? v1 : v0;
        if (v < 0) continue;
        int s = __ldg(offs + v);
        int e = s + __ldg(cnt + v);
        for (int i = s; i < e; i += 32) {
            int m = min(32, e - i);
            int2 md = (lane < m) ? __ldcs(perm + i + lane) : make_int2(0, 0);
            int j = 0;
            for (; j + 3 < m; j += 4) {       // 4-wide MLP
                int   s0 = __shfl_sync(0xffffffffu, md.x, j);
                float c0 = __int_as_float(__shfl_sync(0xffffffffu, md.y, j));
                int   s1 = __shfl_sync(0xffffffffu, md.x, j + 1);
                float c1 = __int_as_float(__shfl_sync(0xffffffffu, md.y, j + 1));
                int   s2 = __shfl_sync(0xffffffffu, md.x, j + 2);
                float c2 = __int_as_float(__shfl_sync(0xffffffffu, md.y, j + 2));
                int   s3 = __shfl_sync(0xffffffffu, md.x, j + 3);
                float c3 = __int_as_float(__shfl_sync(0xffffffffu, md.y, j + 3));
                float4 h0 = __ldg((const float4*)(H + (size_t)s0 * D) + lane);
                float4 h1 = __ldg((const float4*)(H + (size_t)s1 * D) + lane);
                float4 h2 = __ldg((const float4*)(H + (size_t)s2 * D) + lane);
                float4 h3 = __ldg((const float4*)(H + (size_t)s3 * D) + lane);
                acc.x = fmaf(c0, h0.x, fmaf(c1, h1.x, fmaf(c2, h2.x, fmaf(c3, h3.x, acc.x))));
                acc.y = fmaf(c0, h0.y, fmaf(c1, h1.y, fmaf(c2, h2.y, fmaf(c3, h3.y, acc.y))));
                acc.z = fmaf(c0, h0.z, fmaf(c1, h1.z, fmaf(c2, h2.z, fmaf(c3, h3.z, acc.z))));
                acc.w = fmaf(c0, h0.w, fmaf(c1, h1.w, fmaf(c2, h2.w, fmaf(c3, h3.w, acc.w))));
            }
            for (; j < m; j++) {
                int   s0 = __shfl_sync(0xffffffffu, md.x, j);
                float c0 = __int_as_float(__shfl_sync(0xffffffffu, md.y, j));
                edge_fma(acc, s0, c0, H, lane);
            }
        }
    }
    float4 o = make_float4(fmaxf(acc.x, 0.f), fmaxf(acc.y, 0.f),
                           fmaxf(acc.z, 0.f), fmaxf(acc.w, 0.f));
    // evict-first store: keep H resident in L2
    float* p = out + (size_t)row * D + lane * 4;
    asm volatile("st.global.cs.v4.f32 [%0], {%1,%2,%3,%4};"
                 :: "l"(p), "f"(o.x), "f"(o.y), "f"(o.z), "f"(o.w) : "memory");
}

extern "C" void kernel_launch(void* const* d_in, const int* in_sizes, int n_in,
                              void* d_out, int out_size) {
    const float* h_word  = (const float*)d_in[0];
    const float* h_topic = (const float*)d_in[1];
    const float* W_ww = (const float*)d_in[3];
    const float* b_ww = (const float*)d_in[4];
    const float* W_wt = (const float*)d_in[5];
    const float* b_wt = (const float*)d_in[6];
    const float* W_wd = (const float*)d_in[7];
    const float* b_wd = (const float*)d_in[8];
    const float* W_td = (const float*)d_in[9];
    const float* b_td = (const float*)d_in[10];
    const float* W_tt = (const float*)d_in[11];
    const float* b_tt = (const float*)d_in[12];
    const int*   src_ww = (const int*)d_in[13];
    const int*   dst_ww = (const int*)d_in[14];
    const float* ew_ww  = (const float*)d_in[15];
    const int*   src_wt = (const int*)d_in[16];
    const int*   dst_wt = (const int*)d_in[17];
    const float* ew_wt  = (const float*)d_in[18];
    const int*   src_wd = (const int*)d_in[19];
    const int*   dst_wd = (const int*)d_in[20];
    const float* ew_wd  = (const float*)d_in[21];
    const int*   src_td = (const int*)d_in[22];
    const int*   dst_td = (const int*)d_in[23];
    const float* ew_td  = (const float*)d_in[24];
    const int*   src_tt = (const int*)d_in[25];
    const int*   dst_tt = (const int*)d_in[26];
    const float* ew_tt  = (const float*)d_in[27];

    const int E_ww = in_sizes[13];
    const int E_wt = in_sizes[16];
    const int E_wd = in_sizes[19];
    const int E_td = in_sizes[22];
    const int E_tt = in_sizes[25];

    float* out = (float*)d_out;

    float *H, *rcnt;
    int *cnt, *offs, *cursor, *bsum;
    int2* perm;
    cudaGetSymbolAddress((void**)&H, g_h);
    cudaGetSymbolAddress((void**)&cnt, g_cnt);
    cudaGetSymbolAddress((void**)&offs, g_offs);
    cudaGetSymbolAddress((void**)&cursor, g_cursor);
    cudaGetSymbolAddress((void**)&rcnt, g_rcnt);
    cudaGetSymbolAddress((void**)&bsum, g_bsum);
    cudaGetSymbolAddress((void**)&perm, g_perm);

    const int vb_ww = 0;
    const int vb_wt = NW;
    const int vb_tt = NW + NT;
    const int vb_wd = NW + 2 * NT;
    const int vb_td = NW + 2 * NT + ND;

    // fork/join resources (leaked on purpose; ~2 calls total, capture-safe)
    cudaStream_t s2;
    cudaEvent_t evFork, evJoin;
    cudaStreamCreateWithFlags(&s2, cudaStreamNonBlocking);
    cudaEventCreateWithFlags(&evFork, cudaEventDisableTiming);
    cudaEventCreateWithFlags(&evJoin, cudaEventDisableTiming);

    cudaEventRecord(evFork, 0);
    cudaStreamWaitEvent(s2, evFork, 0);

    // ---- side stream: compose -> GEMM ----
    {
        const int csm = (128 * 129 + 128) * (int)sizeof(float);
        cudaFuncSetAttribute(compose1, cudaFuncAttributeMaxDynamicSharedMemorySize, csm);
        cudaFuncSetAttribute(compose2, cudaFuncAttributeMaxDynamicSharedMemorySize, csm);
        compose1<<<258, 128, csm, s2>>>(W_ww, W_wt, b_ww, b_wt, W_td, W_tt, b_td, b_tt);
        compose2<<<129, 128, csm, s2>>>(W_wd, b_wd);
        const int smem_bytes = 139264;
        cudaFuncSetAttribute(gemm_mma, cudaFuncAttributeMaxDynamicSharedMemorySize,
                             smem_bytes);
        gemm_mma<<<TILES_W + TILES_T, 256, smem_bytes, s2>>>(h_word, h_topic, H);
        cudaEventRecord(evJoin, s2);
    }

    // ---- main stream: CSR build chain ----
    cudaMemsetAsync(cnt, 0, NV * sizeof(int), 0);
    {
        Cnt4Args ca;
        ca.dst4[0] = (const int4*)dst_ww; ca.vbase[0] = vb_ww;
        ca.dst4[1] = (const int4*)dst_wt; ca.vbase[1] = vb_wt;
        ca.dst4[2] = (const int4*)dst_tt; ca.vbase[2] = vb_tt;
        ca.dst4[3] = (const int4*)dst_wd; ca.vbase[3] = vb_wd;
        ca.dst4[4] = (const int4*)dst_td; ca.vbase[4] = vb_td;
        ca.cum4[0] = 0;
        ca.cum4[1] = E_ww / 4;
        ca.cum4[2] = ca.cum4[1] + E_wt / 4;
        ca.cum4[3] = ca.cum4[2] + E_tt / 4;
        ca.cum4[4] = ca.cum4[3] + E_wd / 4;
        ca.cum4[5] = ca.cum4[4] + E_td / 4;
        count_all<<<(ca.cum4[5] + 255) / 256, 256>>>(ca, cnt);
    }
    scanA<<<SCAN_BLK, 1024>>>(cnt, NV, offs, rcnt, bsum);
    scanC<<<SCAN_BLK, 1024>>>(offs, NV, bsum, cursor);
    {
        Fill4Args fa;
        fa.src4[0] = (const int4*)src_ww; fa.dst4[0] = (const int4*)dst_ww; fa.ew4[0] = (const float4*)ew_ww; fa.vbase[0] = vb_ww; fa.soff[0] = 0;
        fa.src4[1] = (const int4*)src_wt; fa.dst4[1] = (const int4*)dst_wt; fa.ew4[1] = (const float4*)ew_wt; fa.vbase[1] = vb_wt; fa.soff[1] = 0;
        fa.src4[2] = (const int4*)src_tt; fa.dst4[2] = (const int4*)dst_tt; fa.ew4[2] = (const float4*)ew_tt; fa.vbase[2] = vb_tt; fa.soff[2] = NW;
        fa.src4[3] = (const int4*)src_wd; fa.dst4[3] = (const int4*)dst_wd; fa.ew4[3] = (const float4*)ew_wd; fa.vbase[3] = vb_wd; fa.soff[3] = 0;
        fa.src4[4] = (const int4*)src_td; fa.dst4[4] = (const int4*)dst_td; fa.ew4[4] = (const float4*)ew_td; fa.vbase[4] = vb_td; fa.soff[4] = NW;
        fa.cum4[0] = 0;
        fa.cum4[1] = E_ww / 4;
        fa.cum4[2] = fa.cum4[1] + E_wt / 4;
        fa.cum4[3] = fa.cum4[2] + E_tt / 4;
        fa.cum4[4] = fa.cum4[3] + E_wd / 4;
        fa.cum4[5] = fa.cum4[4] + E_td / 4;
        fill_kernel<<<(fa.cum4[5] + 255) / 256, 256>>>(fa, rcnt, cursor, perm);
    }

    // join: gather needs both H (side) and CSR (main)
    cudaStreamWaitEvent(0, evJoin, 0);
    gather_kernel<<<(NROW * 32 + 255) / 256, 256>>>(perm, offs, cnt, H, out);
}

// round 8
// speedup vs baseline: 1.1369x; 1.1369x over previous
#include <cuda_runtime.h>
#include <cuda_bf16.h>
#include <cstdint>

#define D 128
#define NW 100000
#define NT 10000
#define ND 50000
#define NV (NW + NT + NT + ND + ND)   // 220000 virtual (relation,dst) nodes
#define NROW (NW + NT + ND)           // 160000 output rows
#define SCAN_BLK 54                   // ceil(NV/4096)
#define TILES_W 782                   // ceil(NW/128)
#define TILES_T 79                    // ceil(NT/128)

// ---------------- scratch (device globals: allocation-free) ----------------
__device__ float g_h[(size_t)(NW + NT) * D];  // unified composed features (word|topic)
__device__ int   g_cnt[NV];
__device__ int   g_offs[NV];
__device__ int   g_cursor[NV];
__device__ float g_rcnt[NV];
__device__ int   g_bsum[SCAN_BLK];
__device__ int2  g_perm[600000];
__device__ float g_T1[D * (D + 1)];
__device__ float g_bw[D];
__device__ float g_bt[D];
// composed B, bf16 split, plain [n][k] row-major (n = output dim, k = input dim)
__device__ __nv_bfloat16 g_Bwh[D * D];
__device__ __nv_bfloat16 g_Bwl[D * D];
__device__ __nv_bfloat16 g_Bth[D * D];
__device__ __nv_bfloat16 g_Btl[D * D];

// ---------------- mma/ldmatrix helpers (plain PTX, sm_80+) ----------------
__device__ __forceinline__ uint32_t smem_u32(const void* p) {
    uint32_t a;
    asm("{ .reg .u64 t; cvta.to.shared.u64 t, %1; cvt.u32.u64 %0, t; }" : "=r"(a) : "l"(p));
    return a;
}
__device__ __forceinline__ void ldmx4(uint32_t* r, uint32_t addr) {
    asm volatile("ldmatrix.sync.aligned.m8n8.x4.shared.b16 {%0,%1,%2,%3}, [%4];"
                 : "=r"(r[0]), "=r"(r[1]), "=r"(r[2]), "=r"(r[3]) : "r"(addr));
}
#define MMA_BF16(c0, c1, c2, c3, a0, a1, a2, a3, b0, b1)                        \
    asm volatile(                                                               \
        "mma.sync.aligned.m16n8k16.row.col.f32.bf16.bf16.f32 "                  \
        "{%0,%1,%2,%3}, {%4,%5,%6,%7}, {%8,%9}, {%0,%1,%2,%3};"                 \
        : "+f"(c0), "+f"(c1), "+f"(c2), "+f"(c3)                                \
        : "r"(a0), "r"(a1), "r"(a2), "r"(a3), "r"(b0), "r"(b1))

// ---------------- weight composition ----------------
__global__ void __launch_bounds__(128) compose1(
    const float* __restrict__ Www, const float* __restrict__ Wwt,
    const float* __restrict__ bww, const float* __restrict__ bwt,
    const float* __restrict__ Wtd, const float* __restrict__ Wtt,
    const float* __restrict__ btd, const float* __restrict__ btt) {
    extern __shared__ float sm[];
    float* Ws = sm;
    float* Av = sm + 128 * 129;
    const int b = blockIdx.x;
    const int tid = threadIdx.x;
    const float* Wstage = (b < 129) ? Wwt : Wtt;
#pragma unroll 8
    for (int i = 0; i < 128; i++) Ws[i * 129 + tid] = Wstage[i * 128 + tid];
    if (b < 128)        Av[tid] = Www[tid * 128 + b];
    else if (b == 128)  Av[tid] = bww[tid];
    else if (b < 257)   Av[tid] = Wtd[tid * 128 + (b - 129)];
    else                Av[tid] = btd[tid];
    __syncthreads();
    float s = 0.f;
#pragma unroll 16
    for (int k = 0; k < 128; k++) s += Av[k] * Ws[tid * 129 + k];
    if (b < 128)        g_T1[b * 128 + tid] = s;
    else if (b == 128)  g_T1[128 * 128 + tid] = s + bwt[tid];
    else if (b < 257) {
        int k = b - 129;                  // n = tid, k = input dim
        __nv_bfloat16 hh = __float2bfloat16(s);
        g_Bth[tid * 128 + k] = hh;
        g_Btl[tid * 128 + k] = __float2bfloat16(s - __bfloat162float(hh));
    } else              g_bt[tid] = s + btt[tid];
}
__global__ void __launch_bounds__(128) compose2(
    const float* __restrict__ Wwd, const float* __restrict__ bwd) {
    extern __shared__ float sm[];
    float* Ws = sm;
    float* Av = sm + 128 * 129;
    const int b = blockIdx.x;
    const int tid = threadIdx.x;
#pragma unroll 8
    for (int i = 0; i < 128; i++) Ws[i * 129 + tid] = Wwd[i * 128 + tid];
    Av[tid] = g_T1[b * 128 + tid];
    __syncthreads();
    float s = 0.f;
#pragma unroll 16
    for (int k = 0; k < 128; k++) s += Av[k] * Ws[tid * 129 + k];
    if (b < 128) {
        __nv_bfloat16 hh = __float2bfloat16(s);
        g_Bwh[tid * 128 + b] = hh;
        g_Bwl[tid * 128 + b] = __float2bfloat16(s - __bfloat162float(hh));
    } else g_bw[tid] = s + bwd[tid];
}

// ---------------- tensor-core GEMM: H[M,128] = A @ Bcomp^T + bias --------------
__global__ void __launch_bounds__(256, 1)
gemm_mma(const float* __restrict__ Aw, const float* __restrict__ At,
         float* __restrict__ H) {
    extern __shared__ __align__(16) char smem[];
    __nv_bfloat16* As_hi = (__nv_bfloat16*)smem;                 // [128][136]
    __nv_bfloat16* As_lo = (__nv_bfloat16*)(smem + 34816);
    __nv_bfloat16* Bs_hi = (__nv_bfloat16*)(smem + 69632);
    __nv_bfloat16* Bs_lo = (__nv_bfloat16*)(smem + 104448);
    const int tid = threadIdx.x;
    const int wid = tid >> 5, lane = tid & 31;

    const float* A;
    const __nv_bfloat16 *Bh, *Bl;
    const float* bias;
    float* C;
    int M, row0;
    if (blockIdx.x < TILES_W) {
        A = Aw; Bh = g_Bwh; Bl = g_Bwl; bias = g_bw; C = H;
        M = NW; row0 = blockIdx.x * 128;
    } else {
        A = At; Bh = g_Bth; Bl = g_Btl; bias = g_bt; C = H + (size_t)NW * D;
        M = NT; row0 = (blockIdx.x - TILES_W) * 128;
    }

    {
        const uint32_t* bh = (const uint32_t*)Bh;
        const uint32_t* bl = (const uint32_t*)Bl;
        uint32_t* dh = (uint32_t*)Bs_hi;
        uint32_t* dl = (uint32_t*)Bs_lo;
#pragma unroll
        for (int i = 0; i < 32; i++) {
            int idx = tid + 256 * i;
            int n = idx >> 6, w = idx & 63;
            dh[n * 68 + w] = __ldg(bh + idx);
            dl[n * 68 + w] = __ldg(bl + idx);
        }
    }
    {
#pragma unroll
        for (int i = 0; i < 16; i++) {
            int idx = tid + 256 * i;
            int r = idx >> 5, c4 = idx & 31;
            float4 f = (row0 + r < M)
                ? __ldg((const float4*)(A + (size_t)(row0 + r) * D) + c4)
                : make_float4(0.f, 0.f, 0.f, 0.f);
            __nv_bfloat16 h0 = __float2bfloat16(f.x), h1 = __float2bfloat16(f.y);
            __nv_bfloat16 h2 = __float2bfloat16(f.z), h3 = __float2bfloat16(f.w);
            __nv_bfloat162 ph0, ph1, pl0, pl1;
            ph0.x = h0; ph0.y = h1; ph1.x = h2; ph1.y = h3;
            pl0.x = __float2bfloat16(f.x - __bfloat162float(h0));
            pl0.y = __float2bfloat16(f.y - __bfloat162float(h1));
            pl1.x = __float2bfloat16(f.z - __bfloat162float(h2));
            pl1.y = __float2bfloat16(f.w - __bfloat162float(h3));
            int base = r * 136 + c4 * 4;
            *(__nv_bfloat162*)(As_hi + base)     = ph0;
            *(__nv_bfloat162*)(As_hi + base + 2) = ph1;
            *(__nv_bfloat162*)(As_lo + base)     = pl0;
            *(__nv_bfloat162*)(As_lo + base + 2) = pl1;
        }
    }
    __syncthreads();

    const uint32_t as_hi_b = smem_u32(As_hi), as_lo_b = smem_u32(As_lo);
    const uint32_t bs_hi_b = smem_u32(Bs_hi), bs_lo_b = smem_u32(Bs_lo);
    const int lr = lane & 7, lm = lane >> 3;

    uint32_t ah[8][4], al[8][4];
    {
        uint32_t arow = (uint32_t)(wid * 16 + lr + (lm & 1) * 8);
        uint32_t acol = (uint32_t)((lm >> 1) * 8);
        uint32_t abase = (arow * 136 + acol) * 2;
#pragma unroll
        for (int ks = 0; ks < 8; ks++) {
            ldmx4(ah[ks], as_hi_b + abase + ks * 32);
            ldmx4(al[ks], as_lo_b + abase + ks * 32);
        }
    }

    const int g = lane >> 2, t = lane & 3;
    const int orow0 = row0 + wid * 16 + g;
    const uint32_t bbase_sel = (lm >= 2) ? bs_lo_b : bs_hi_b;
    const uint32_t bcol = (uint32_t)((lm & 1) * 8);

#pragma unroll 4
    for (int nt = 0; nt < 16; nt++) {
        float c0 = 0.f, c1 = 0.f, c2 = 0.f, c3 = 0.f;
        uint32_t baddr = bbase_sel + (((uint32_t)(nt * 8 + lr)) * 136 + bcol) * 2;
#pragma unroll
        for (int ks = 0; ks < 8; ks++) {
            uint32_t b[4];
            ldmx4(b, baddr + ks * 32);
            MMA_BF16(c0, c1, c2, c3, ah[ks][0], ah[ks][1], ah[ks][2], ah[ks][3], b[0], b[1]);
            MMA_BF16(c0, c1, c2, c3, al[ks][0], al[ks][1], al[ks][2], al[ks][3], b[0], b[1]);
            MMA_BF16(c0, c1, c2, c3, ah[ks][0], ah[ks][1], ah[ks][2], ah[ks][3], b[2], b[3]);
        }
        int col = nt * 8 + t * 2;
        float2 b2 = __ldg((const float2*)(bias + col));
        if (orow0 < M)
            *(float2*)(C + (size_t)orow0 * D + col) = make_float2(c0 + b2.x, c1 + b2.y);
        if (orow0 + 8 < M)
            *(float2*)(C + (size_t)(orow0 + 8) * D + col) = make_float2(c2 + b2.x, c3 + b2.y);
    }
}

// ---------------- counts (int4 vectorized, fire-and-forget) ----------------
struct Cnt4Args {
    const int4* dst4[5];
    int vbase[5];
    int cum4[6];
};
__global__ void count_all(Cnt4Args a, int* __restrict__ cnt) {
    int g = blockIdx.x * blockDim.x + threadIdx.x;
    if (g >= a.cum4[5]) return;
    int r = 0;
    while (g >= a.cum4[r + 1]) r++;
    int4 d = __ldcs(a.dst4[r] + (g - a.cum4[r]));
    int* base = cnt + a.vbase[r];
    atomicAdd(base + d.x, 1);
    atomicAdd(base + d.y, 1);
    atomicAdd(base + d.z, 1);
    atomicAdd(base + d.w, 1);
}

// ---------------- scan pass A: per-block exclusive scan + rcnt --------------
__global__ void __launch_bounds__(1024) scanA(const int* __restrict__ cnt, int n,
                                              int* __restrict__ offs,
                                              float* __restrict__ rcnt,
                                              int* __restrict__ bsum) {
    __shared__ int wsum[32];
    const int tid = threadIdx.x;
    const int base = blockIdx.x * 4096 + tid * 4;
    int v[4];
#pragma unroll
    for (int k = 0; k < 4; k++) v[k] = (base + k < n) ? cnt[base + k] : 0;
#pragma unroll
    for (int k = 0; k < 4; k++)
        if (base + k < n) rcnt[base + k] = 1.0f / (float)max(v[k], 1);
    int t = v[0] + v[1] + v[2] + v[3];
    const int lane = tid & 31, w = tid >> 5;
    int inc = t;
#pragma unroll
    for (int dlt = 1; dlt < 32; dlt <<= 1) {
        int x = __shfl_up_sync(0xffffffffu, inc, dlt);
        if (lane >= dlt) inc += x;
    }
    if (lane == 31) wsum[w] = inc;
    __syncthreads();
    if (w == 0) {
        int si = wsum[lane];
#pragma unroll
        for (int dlt = 1; dlt < 32; dlt <<= 1) {
            int x = __shfl_up_sync(0xffffffffu, si, dlt);
            if (lane >= dlt) si += x;
        }
        wsum[lane] = si;
    }
    __syncthreads();
    int o = inc - t + (w > 0 ? wsum[w - 1] : 0);
#pragma unroll
    for (int k = 0; k < 4; k++) {
        if (base + k < n) offs[base + k] = o;
        o += v[k];
    }
    if (tid == 0) bsum[blockIdx.x] = wsum[31];
}

// ---------------- scan pass C (merged B): add block-prefix, init cursors ----
__global__ void __launch_bounds__(1024) scanC(int* __restrict__ offs, int n,
                                              const int* __restrict__ bsum,
                                              int* __restrict__ cursor) {
    __shared__ int pref;
    const int tid = threadIdx.x;
    if (tid < 32) {
        int acc = 0;
        for (int i = tid; i < blockIdx.x; i += 32) acc += bsum[i];
#pragma unroll
        for (int dlt = 16; dlt > 0; dlt >>= 1)
            acc += __shfl_down_sync(0xffffffffu, acc, dlt);
        if (tid == 0) pref = acc;
    }
    __syncthreads();
    const int add = pref;
    int base = blockIdx.x * 4096 + tid * 4;
#pragma unroll
    for (int k = 0; k < 4; k++) {
        int i = base + k;
        if (i < n) {
            int o = offs[i] + add;
            offs[i] = o;
            cursor[i] = o;
        }
    }
}

// ---------------- CSR fill (4 edges/thread, vectorized) ----------------
struct Fill4Args {
    const int4*   src4[5];
    const int4*   dst4[5];
    const float4* ew4[5];
    int vbase[5];
    int soff[5];
    int cum4[6];
};
__global__ void fill_kernel(Fill4Args a, const float* __restrict__ rcnt,
                            int* __restrict__ cursor, int2* __restrict__ perm) {
    int g = blockIdx.x * blockDim.x + threadIdx.x;
    if (g >= a.cum4[5]) return;
    int r = 0;
    while (g >= a.cum4[r + 1]) r++;
    int e4 = g - a.cum4[r];
    int4   s = __ldcs(a.src4[r] + e4);
    int4   d = __ldcs(a.dst4[r] + e4);
    float4 w = __ldcs(a.ew4[r] + e4);
    const int vb = a.vbase[r], so = a.soff[r];
    {
        int v = vb + d.x;
        int pos = atomicAdd(cursor + v, 1);
        perm[pos] = make_int2(s.x + so, __float_as_int(w.x * __ldg(rcnt + v)));
    }
    {
        int v = vb + d.y;
        int pos = atomicAdd(cursor + v, 1);
        perm[pos] = make_int2(s.y + so, __float_as_int(w.y * __ldg(rcnt + v)));
    }
    {
        int v = vb + d.z;
        int pos = atomicAdd(cursor + v, 1);
        perm[pos] = make_int2(s.z + so, __float_as_int(w.z * __ldg(rcnt + v)));
    }
    {
        int v = vb + d.w;
        int pos = atomicAdd(cursor + v, 1);
        perm[pos] = make_int2(s.w + so, __float_as_int(w.w * __ldg(rcnt + v)));
    }
}

// ---------------- gather: one warp per output row, fused relu (R6 form) -----
__global__ void __launch_bounds__(256) gather_kernel(
    const int2* __restrict__ perm, const int* __restrict__ offs,
    const int* __restrict__ cnt, const float* __restrict__ H,
    float* __restrict__ out) {
    int gid = blockIdx.x * 256 + threadIdx.x;
    int row = gid >> 5;
    if (row >= NROW) return;
    int lane = gid & 31;

    int v0, v1;
    if (row < NW) { v0 = row; v1 = -1; }
    else if (row < NW + NT) { int t = row - NW; v0 = NW + t; v1 = NW + NT + t; }
    else { int d = row - NW - NT; v0 = NW + 2 * NT + d; v1 = NW + 2 * NT + ND + d; }

    float4 acc = make_float4(0.f, 0.f, 0.f, 0.f);
#pragma unroll
    for (int pass = 0; pass < 2; pass++) {
        int v = pass ? v1 : v0;
        if (v < 0) continue;
        int s = __ldg(offs + v);
        int e = s + __ldg(cnt + v);
        for (int i = s; i < e; i += 32) {
            int m = min(32, e - i);
            int2 md = (lane < m) ? __ldg(perm + i + lane) : make_int2(0, 0);
            int j = 0;
            for (; j + 1 < m; j += 2) {
                int s0 = __shfl_sync(0xffffffffu, md.x, j);
                float c0 = __int_as_float(__shfl_sync(0xffffffffu, md.y, j));
                int s1 = __shfl_sync(0xffffffffu, md.x, j + 1);
                float c1 = __int_as_float(__shfl_sync(0xffffffffu, md.y, j + 1));
                float4 h0 = __ldg((const float4*)(H + (size_t)s0 * D) + lane);
                float4 h1 = __ldg((const float4*)(H + (size_t)s1 * D) + lane);
                acc.x = fmaf(c0, h0.x, fmaf(c1, h1.x, acc.x));
                acc.y = fmaf(c0, h0.y, fmaf(c1, h1.y, acc.y));
                acc.z = fmaf(c0, h0.z, fmaf(c1, h1.z, acc.z));
                acc.w = fmaf(c0, h0.w, fmaf(c1, h1.w, acc.w));
            }
            if (j < m) {
                int s0 = __shfl_sync(0xffffffffu, md.x, j);
                float c0 = __int_as_float(__shfl_sync(0xffffffffu, md.y, j));
                float4 h0 = __ldg((const float4*)(H + (size_t)s0 * D) + lane);
                acc.x = fmaf(c0, h0.x, acc.x);
                acc.y = fmaf(c0, h0.y, acc.y);
                acc.z = fmaf(c0, h0.z, acc.z);
                acc.w = fmaf(c0, h0.w, acc.w);
            }
        }
    }
    float4 o = make_float4(fmaxf(acc.x, 0.f), fmaxf(acc.y, 0.f),
                           fmaxf(acc.z, 0.f), fmaxf(acc.w, 0.f));
    *(float4*)(out + (size_t)row * D + lane * 4) = o;
}

extern "C" void kernel_launch(void* const* d_in, const int* in_sizes, int n_in,
                              void* d_out, int out_size) {
    const float* h_word  = (const float*)d_in[0];
    const float* h_topic = (const float*)d_in[1];
    const float* W_ww = (const float*)d_in[3];
    const float* b_ww = (const float*)d_in[4];
    const float* W_wt = (const float*)d_in[5];
    const float* b_wt = (const float*)d_in[6];
    const float* W_wd = (const float*)d_in[7];
    const float* b_wd = (const float*)d_in[8];
    const float* W_td = (const float*)d_in[9];
    const float* b_td = (const float*)d_in[10];
    const float* W_tt = (const float*)d_in[11];
    const float* b_tt = (const float*)d_in[12];
    const int*   src_ww = (const int*)d_in[13];
    const int*   dst_ww = (const int*)d_in[14];
    const float* ew_ww  = (const float*)d_in[15];
    const int*   src_wt = (const int*)d_in[16];
    const int*   dst_wt = (const int*)d_in[17];
    const float* ew_wt  = (const float*)d_in[18];
    const int*   src_wd = (const int*)d_in[19];
    const int*   dst_wd = (const int*)d_in[20];
    const float* ew_wd  = (const float*)d_in[21];
    const int*   src_td = (const int*)d_in[22];
    const int*   dst_td = (const int*)d_in[23];
    const float* ew_td  = (const float*)d_in[24];
    const int*   src_tt = (const int*)d_in[25];
    const int*   dst_tt = (const int*)d_in[26];
    const float* ew_tt  = (const float*)d_in[27];

    const int E_ww = in_sizes[13];
    const int E_wt = in_sizes[16];
    const int E_wd = in_sizes[19];
    const int E_td = in_sizes[22];
    const int E_tt = in_sizes[25];

    float* out = (float*)d_out;

    float *H, *rcnt;
    int *cnt, *offs, *cursor, *bsum;
    int2* perm;
    cudaGetSymbolAddress((void**)&H, g_h);
    cudaGetSymbolAddress((void**)&cnt, g_cnt);
    cudaGetSymbolAddress((void**)&offs, g_offs);
    cudaGetSymbolAddress((void**)&cursor, g_cursor);
    cudaGetSymbolAddress((void**)&rcnt, g_rcnt);
    cudaGetSymbolAddress((void**)&bsum, g_bsum);
    cudaGetSymbolAddress((void**)&perm, g_perm);

    const int vb_ww = 0;
    const int vb_wt = NW;
    const int vb_tt = NW + NT;
    const int vb_wd = NW + 2 * NT;
    const int vb_td = NW + 2 * NT + ND;

    // fork/join resources (leaked on purpose; ~2 calls total, capture-safe)
    cudaStream_t s2;
    cudaEvent_t evFork, evJoin;
    cudaStreamCreateWithFlags(&s2, cudaStreamNonBlocking);
    cudaEventCreateWithFlags(&evFork, cudaEventDisableTiming);
    cudaEventCreateWithFlags(&evJoin, cudaEventDisableTiming);

    cudaEventRecord(evFork, 0);
    cudaStreamWaitEvent(s2, evFork, 0);

    // ---- side stream: compose -> GEMM ----
    {
        const int csm = (128 * 129 + 128) * (int)sizeof(float);
        cudaFuncSetAttribute(compose1, cudaFuncAttributeMaxDynamicSharedMemorySize, csm);
        cudaFuncSetAttribute(compose2, cudaFuncAttributeMaxDynamicSharedMemorySize, csm);
        compose1<<<258, 128, csm, s2>>>(W_ww, W_wt, b_ww, b_wt, W_td, W_tt, b_td, b_tt);
        compose2<<<129, 128, csm, s2>>>(W_wd, b_wd);
        const int smem_bytes = 139264;
        cudaFuncSetAttribute(gemm_mma, cudaFuncAttributeMaxDynamicSharedMemorySize,
                             smem_bytes);
        gemm_mma<<<TILES_W + TILES_T, 256, smem_bytes, s2>>>(h_word, h_topic, H);
        cudaEventRecord(evJoin, s2);
    }

    // ---- main stream: CSR build chain ----
    cudaMemsetAsync(cnt, 0, NV * sizeof(int), 0);
    {
        Cnt4Args ca;
        ca.dst4[0] = (const int4*)dst_ww; ca.vbase[0] = vb_ww;
        ca.dst4[1] = (const int4*)dst_wt; ca.vbase[1] = vb_wt;
        ca.dst4[2] = (const int4*)dst_tt; ca.vbase[2] = vb_tt;
        ca.dst4[3] = (const int4*)dst_wd; ca.vbase[3] = vb_wd;
        ca.dst4[4] = (const int4*)dst_td; ca.vbase[4] = vb_td;
        ca.cum4[0] = 0;
        ca.cum4[1] = E_ww / 4;
        ca.cum4[2] = ca.cum4[1] + E_wt / 4;
        ca.cum4[3] = ca.cum4[2] + E_tt / 4;
        ca.cum4[4] = ca.cum4[3] + E_wd / 4;
        ca.cum4[5] = ca.cum4[4] + E_td / 4;
        count_all<<<(ca.cum4[5] + 255) / 256, 256>>>(ca, cnt);
    }
    scanA<<<SCAN_BLK, 1024>>>(cnt, NV, offs, rcnt, bsum);
    scanC<<<SCAN_BLK, 1024>>>(offs, NV, bsum, cursor);
    {
        Fill4Args fa;
        fa.src4[0] = (const int4*)src_ww; fa.dst4[0] = (const int4*)dst_ww; fa.ew4[0] = (const float4*)ew_ww; fa.vbase[0] = vb_ww; fa.soff[0] = 0;
        fa.src4[1] = (const int4*)src_wt; fa.dst4[1] = (const int4*)dst_wt; fa.ew4[1] = (const float4*)ew_wt; fa.vbase[1] = vb_wt; fa.soff[1] = 0;
        fa.src4[2] = (const int4*)src_tt; fa.dst4[2] = (const int4*)dst_tt; fa.ew4[2] = (const float4*)ew_tt; fa.vbase[2] = vb_tt; fa.soff[2] = NW;
        fa.src4[3] = (const int4*)src_wd; fa.dst4[3] = (const int4*)dst_wd; fa.ew4[3] = (const float4*)ew_wd; fa.vbase[3] = vb_wd; fa.soff[3] = 0;
        fa.src4[4] = (const int4*)src_td; fa.dst4[4] = (const int4*)dst_td; fa.ew4[4] = (const float4*)ew_td; fa.vbase[4] = vb_td; fa.soff[4] = NW;
        fa.cum4[0] = 0;
        fa.cum4[1] = E_ww / 4;
        fa.cum4[2] = fa.cum4[1] + E_wt / 4;
        fa.cum4[3] = fa.cum4[2] + E_tt / 4;
        fa.cum4[4] = fa.cum4[3] + E_wd / 4;
        fa.cum4[5] = fa.cum4[4] + E_td / 4;
        fill_kernel<<<(fa.cum4[5] + 255) / 256, 256>>>(fa, rcnt, cursor, perm);
    }

    // join: gather needs both H (side) and CSR (main)
    cudaStreamWaitEvent(0, evJoin, 0);
    gather_kernel<<<(NROW * 32 + 255) / 256, 256>>>(perm, offs, cnt, H, out);
}

// round 9
// speedup vs baseline: 1.2028x; 1.0580x over previous
#include <cuda_runtime.h>
#include <cuda_bf16.h>
#include <cuda_fp16.h>
#include <cstdint>

#define D 128
#define NW 100000
#define NT 10000
#define ND 50000
#define NV (NW + NT + NT + ND + ND)   // 220000 virtual (relation,dst) nodes
#define NROW (NW + NT + ND)           // 160000 output rows
#define SCAN_BLK 54                   // ceil(NV/4096)
#define TILES_W 782                   // ceil(NW/128)
#define TILES_T 79                    // ceil(NT/128)

// ---------------- scratch (device globals: allocation-free) ----------------
__device__ __half g_h[(size_t)(NW + NT) * D];  // unified composed features, fp16
__device__ int   g_cnt[NV];
__device__ int   g_offs[NV];
__device__ int   g_cursor[NV];
__device__ float g_rcnt[NV];
__device__ int   g_bsum[SCAN_BLK];
__device__ int2  g_perm[600000];
__device__ float g_T1[D * (D + 1)];
__device__ float g_bw[D];
__device__ float g_bt[D];
// composed B, bf16 split, plain [n][k] row-major
__device__ __nv_bfloat16 g_Bwh[D * D];
__device__ __nv_bfloat16 g_Bwl[D * D];
__device__ __nv_bfloat16 g_Bth[D * D];
__device__ __nv_bfloat16 g_Btl[D * D];

// ---------------- mma/ldmatrix helpers (plain PTX, sm_80+) ----------------
__device__ __forceinline__ uint32_t smem_u32(const void* p) {
    uint32_t a;
    asm("{ .reg .u64 t; cvta.to.shared.u64 t, %1; cvt.u32.u64 %0, t; }" : "=r"(a) : "l"(p));
    return a;
}
__device__ __forceinline__ void ldmx4(uint32_t* r, uint32_t addr) {
    asm volatile("ldmatrix.sync.aligned.m8n8.x4.shared.b16 {%0,%1,%2,%3}, [%4];"
                 : "=r"(r[0]), "=r"(r[1]), "=r"(r[2]), "=r"(r[3]) : "r"(addr));
}
#define MMA_BF16(c0, c1, c2, c3, a0, a1, a2, a3, b0, b1)                        \
    asm volatile(                                                               \
        "mma.sync.aligned.m16n8k16.row.col.f32.bf16.bf16.f32 "                  \
        "{%0,%1,%2,%3}, {%4,%5,%6,%7}, {%8,%9}, {%0,%1,%2,%3};"                 \
        : "+f"(c0), "+f"(c1), "+f"(c2), "+f"(c3)                                \
        : "r"(a0), "r"(a1), "r"(a2), "r"(a3), "r"(b0), "r"(b1))

// ---------------- weight composition ----------------
__global__ void __launch_bounds__(128) compose1(
    const float* __restrict__ Www, const float* __restrict__ Wwt,
    const float* __restrict__ bww, const float* __restrict__ bwt,
    const float* __restrict__ Wtd, const float* __restrict__ Wtt,
    const float* __restrict__ btd, const float* __restrict__ btt) {
    extern __shared__ float sm[];
    float* Ws = sm;
    float* Av = sm + 128 * 129;
    const int b = blockIdx.x;
    const int tid = threadIdx.x;
    const float* Wstage = (b < 129) ? Wwt : Wtt;
#pragma unroll 8
    for (int i = 0; i < 128; i++) Ws[i * 129 + tid] = Wstage[i * 128 + tid];
    if (b < 128)        Av[tid] = Www[tid * 128 + b];
    else if (b == 128)  Av[tid] = bww[tid];
    else if (b < 257)   Av[tid] = Wtd[tid * 128 + (b - 129)];
    else                Av[tid] = btd[tid];
    __syncthreads();
    float s = 0.f;
#pragma unroll 16
    for (int k = 0; k < 128; k++) s += Av[k] * Ws[tid * 129 + k];
    if (b < 128)        g_T1[b * 128 + tid] = s;
    else if (b == 128)  g_T1[128 * 128 + tid] = s + bwt[tid];
    else if (b < 257) {
        int k = b - 129;
        __nv_bfloat16 hh = __float2bfloat16(s);
        g_Bth[tid * 128 + k] = hh;
        g_Btl[tid * 128 + k] = __float2bfloat16(s - __bfloat162float(hh));
    } else              g_bt[tid] = s + btt[tid];
}
__global__ void __launch_bounds__(128) compose2(
    const float* __restrict__ Wwd, const float* __restrict__ bwd) {
    extern __shared__ float sm[];
    float* Ws = sm;
    float* Av = sm + 128 * 129;
    const int b = blockIdx.x;
    const int tid = threadIdx.x;
#pragma unroll 8
    for (int i = 0; i < 128; i++) Ws[i * 129 + tid] = Wwd[i * 128 + tid];
    Av[tid] = g_T1[b * 128 + tid];
    __syncthreads();
    float s = 0.f;
#pragma unroll 16
    for (int k = 0; k < 128; k++) s += Av[k] * Ws[tid * 129 + k];
    if (b < 128) {
        __nv_bfloat16 hh = __float2bfloat16(s);
        g_Bwh[tid * 128 + b] = hh;
        g_Bwl[tid * 128 + b] = __float2bfloat16(s - __bfloat162float(hh));
    } else g_bw[tid] = s + bwd[tid];
}

// ---------------- tensor-core GEMM: H[M,128] = A @ Bcomp^T + bias (fp16 out) ----
__global__ void __launch_bounds__(256, 1)
gemm_mma(const float* __restrict__ Aw, const float* __restrict__ At,
         __half* __restrict__ H) {
    extern __shared__ __align__(16) char smem[];
    __nv_bfloat16* As_hi = (__nv_bfloat16*)smem;                 // [128][136]
    __nv_bfloat16* As_lo = (__nv_bfloat16*)(smem + 34816);
    __nv_bfloat16* Bs_hi = (__nv_bfloat16*)(smem + 69632);
    __nv_bfloat16* Bs_lo = (__nv_bfloat16*)(smem + 104448);
    const int tid = threadIdx.x;
    const int wid = tid >> 5, lane = tid & 31;

    const float* A;
    const __nv_bfloat16 *Bh, *Bl;
    const float* bias;
    __half* C;
    int M, row0;
    if (blockIdx.x < TILES_W) {
        A = Aw; Bh = g_Bwh; Bl = g_Bwl; bias = g_bw; C = H;
        M = NW; row0 = blockIdx.x * 128;
    } else {
        A = At; Bh = g_Bth; Bl = g_Btl; bias = g_bt; C = H + (size_t)NW * D;
        M = NT; row0 = (blockIdx.x - TILES_W) * 128;
    }

    {
        const uint32_t* bh = (const uint32_t*)Bh;
        const uint32_t* bl = (const uint32_t*)Bl;
        uint32_t* dh = (uint32_t*)Bs_hi;
        uint32_t* dl = (uint32_t*)Bs_lo;
#pragma unroll
        for (int i = 0; i < 32; i++) {
            int idx = tid + 256 * i;
            int n = idx >> 6, w = idx & 63;
            dh[n * 68 + w] = __ldg(bh + idx);
            dl[n * 68 + w] = __ldg(bl + idx);
        }
    }
    {
#pragma unroll
        for (int i = 0; i < 16; i++) {
            int idx = tid + 256 * i;
            int r = idx >> 5, c4 = idx & 31;
            float4 f = (row0 + r < M)
                ? __ldg((const float4*)(A + (size_t)(row0 + r) * D) + c4)
                : make_float4(0.f, 0.f, 0.f, 0.f);
            __nv_bfloat16 h0 = __float2bfloat16(f.x), h1 = __float2bfloat16(f.y);
            __nv_bfloat16 h2 = __float2bfloat16(f.z), h3 = __float2bfloat16(f.w);
            __nv_bfloat162 ph0, ph1, pl0, pl1;
            ph0.x = h0; ph0.y = h1; ph1.x = h2; ph1.y = h3;
            pl0.x = __float2bfloat16(f.x - __bfloat162float(h0));
            pl0.y = __float2bfloat16(f.y - __bfloat162float(h1));
            pl1.x = __float2bfloat16(f.z - __bfloat162float(h2));
            pl1.y = __float2bfloat16(f.w - __bfloat162float(h3));
            int base = r * 136 + c4 * 4;
            *(__nv_bfloat162*)(As_hi + base)     = ph0;
            *(__nv_bfloat162*)(As_hi + base + 2) = ph1;
            *(__nv_bfloat162*)(As_lo + base)     = pl0;
            *(__nv_bfloat162*)(As_lo + base + 2) = pl1;
        }
    }
    __syncthreads();

    const uint32_t as_hi_b = smem_u32(As_hi), as_lo_b = smem_u32(As_lo);
    const uint32_t bs_hi_b = smem_u32(Bs_hi), bs_lo_b = smem_u32(Bs_lo);
    const int lr = lane & 7, lm = lane >> 3;

    uint32_t ah[8][4], al[8][4];
    {
        uint32_t arow = (uint32_t)(wid * 16 + lr + (lm & 1) * 8);
        uint32_t acol = (uint32_t)((lm >> 1) * 8);
        uint32_t abase = (arow * 136 + acol) * 2;
#pragma unroll
        for (int ks = 0; ks < 8; ks++) {
            ldmx4(ah[ks], as_hi_b + abase + ks * 32);
            ldmx4(al[ks], as_lo_b + abase + ks * 32);
        }
    }

    const int g = lane >> 2, t = lane & 3;
    const int orow0 = row0 + wid * 16 + g;
    const uint32_t bbase_sel = (lm >= 2) ? bs_lo_b : bs_hi_b;
    const uint32_t bcol = (uint32_t)((lm & 1) * 8);

#pragma unroll 4
    for (int nt = 0; nt < 16; nt++) {
        float c0 = 0.f, c1 = 0.f, c2 = 0.f, c3 = 0.f;
        uint32_t baddr = bbase_sel + (((uint32_t)(nt * 8 + lr)) * 136 + bcol) * 2;
#pragma unroll
        for (int ks = 0; ks < 8; ks++) {
            uint32_t b[4];
            ldmx4(b, baddr + ks * 32);
            MMA_BF16(c0, c1, c2, c3, ah[ks][0], ah[ks][1], ah[ks][2], ah[ks][3], b[0], b[1]);
            MMA_BF16(c0, c1, c2, c3, al[ks][0], al[ks][1], al[ks][2], al[ks][3], b[0], b[1]);
            MMA_BF16(c0, c1, c2, c3, ah[ks][0], ah[ks][1], ah[ks][2], ah[ks][3], b[2], b[3]);
        }
        int col = nt * 8 + t * 2;
        float2 b2 = __ldg((const float2*)(bias + col));
        if (orow0 < M)
            *(__half2*)(C + (size_t)orow0 * D + col) =
                __floats2half2_rn(c0 + b2.x, c1 + b2.y);
        if (orow0 + 8 < M)
            *(__half2*)(C + (size_t)(orow0 + 8) * D + col) =
                __floats2half2_rn(c2 + b2.x, c3 + b2.y);
    }
}

// ---------------- counts (int4 vectorized, fire-and-forget) ----------------
struct Cnt4Args {
    const int4* dst4[5];
    int vbase[5];
    int cum4[6];
};
__global__ void count_all(Cnt4Args a, int* __restrict__ cnt) {
    int g = blockIdx.x * blockDim.x + threadIdx.x;
    if (g >= a.cum4[5]) return;
    int r = 0;
    while (g >= a.cum4[r + 1]) r++;
    int4 d = __ldcs(a.dst4[r] + (g - a.cum4[r]));
    int* base = cnt + a.vbase[r];
    atomicAdd(base + d.x, 1);
    atomicAdd(base + d.y, 1);
    atomicAdd(base + d.z, 1);
    atomicAdd(base + d.w, 1);
}

// ---------------- scan pass A ----------------
__global__ void __launch_bounds__(1024) scanA(const int* __restrict__ cnt, int n,
                                              int* __restrict__ offs,
                                              float* __restrict__ rcnt,
                                              int* __restrict__ bsum) {
    __shared__ int wsum[32];
    const int tid = threadIdx.x;
    const int base = blockIdx.x * 4096 + tid * 4;
    int v[4];
#pragma unroll
    for (int k = 0; k < 4; k++) v[k] = (base + k < n) ? cnt[base + k] : 0;
#pragma unroll
    for (int k = 0; k < 4; k++)
        if (base + k < n) rcnt[base + k] = 1.0f / (float)max(v[k], 1);
    int t = v[0] + v[1] + v[2] + v[3];
    const int lane = tid & 31, w = tid >> 5;
    int inc = t;
#pragma unroll
    for (int dlt = 1; dlt < 32; dlt <<= 1) {
        int x = __shfl_up_sync(0xffffffffu, inc, dlt);
        if (lane >= dlt) inc += x;
    }
    if (lane == 31) wsum[w] = inc;
    __syncthreads();
    if (w == 0) {
        int si = wsum[lane];
#pragma unroll
        for (int dlt = 1; dlt < 32; dlt <<= 1) {
            int x = __shfl_up_sync(0xffffffffu, si, dlt);
            if (lane >= dlt) si += x;
        }
        wsum[lane] = si;
    }
    __syncthreads();
    int o = inc - t + (w > 0 ? wsum[w - 1] : 0);
#pragma unroll
    for (int k = 0; k < 4; k++) {
        if (base + k < n) offs[base + k] = o;
        o += v[k];
    }
    if (tid == 0) bsum[blockIdx.x] = wsum[31];
}

// ---------------- scan pass C (merged B) ----------------
__global__ void __launch_bounds__(1024) scanC(int* __restrict__ offs, int n,
                                              const int* __restrict__ bsum,
                                              int* __restrict__ cursor) {
    __shared__ int pref;
    const int tid = threadIdx.x;
    if (tid < 32) {
        int acc = 0;
        for (int i = tid; i < blockIdx.x; i += 32) acc += bsum[i];
#pragma unroll
        for (int dlt = 16; dlt > 0; dlt >>= 1)
            acc += __shfl_down_sync(0xffffffffu, acc, dlt);
        if (tid == 0) pref = acc;
    }
    __syncthreads();
    const int add = pref;
    int base = blockIdx.x * 4096 + tid * 4;
#pragma unroll
    for (int k = 0; k < 4; k++) {
        int i = base + k;
        if (i < n) {
            int o = offs[i] + add;
            offs[i] = o;
            cursor[i] = o;
        }
    }
}

// ---------------- CSR fill (4 edges/thread, vectorized) ----------------
struct Fill4Args {
    const int4*   src4[5];
    const int4*   dst4[5];
    const float4* ew4[5];
    int vbase[5];
    int soff[5];
    int cum4[6];
};
__global__ void fill_kernel(Fill4Args a, const float* __restrict__ rcnt,
                            int* __restrict__ cursor, int2* __restrict__ perm) {
    int g = blockIdx.x * blockDim.x + threadIdx.x;
    if (g >= a.cum4[5]) return;
    int r = 0;
    while (g >= a.cum4[r + 1]) r++;
    int e4 = g - a.cum4[r];
    int4   s = __ldcs(a.src4[r] + e4);
    int4   d = __ldcs(a.dst4[r] + e4);
    float4 w = __ldcs(a.ew4[r] + e4);
    const int vb = a.vbase[r], so = a.soff[r];
    {
        int v = vb + d.x;
        int pos = atomicAdd(cursor + v, 1);
        perm[pos] = make_int2(s.x + so, __float_as_int(w.x * __ldg(rcnt + v)));
    }
    {
        int v = vb + d.y;
        int pos = atomicAdd(cursor + v, 1);
        perm[pos] = make_int2(s.y + so, __float_as_int(w.y * __ldg(rcnt + v)));
    }
    {
        int v = vb + d.z;
        int pos = atomicAdd(cursor + v, 1);
        perm[pos] = make_int2(s.z + so, __float_as_int(w.z * __ldg(rcnt + v)));
    }
    {
        int v = vb + d.w;
        int pos = atomicAdd(cursor + v, 1);
        perm[pos] = make_int2(s.w + so, __float_as_int(w.w * __ldg(rcnt + v)));
    }
}

// ---------------- gather: one warp per output row, fp16 H, fused relu -------
__device__ __forceinline__ void h_fma(float4& acc, float c,
                                      const __half* __restrict__ Hrow, int lane) {
    uint2 raw = __ldg((const uint2*)Hrow + lane);
    float2 f0 = __half22float2(*(__half2*)&raw.x);
    float2 f1 = __half22float2(*(__half2*)&raw.y);
    acc.x = fmaf(c, f0.x, acc.x);
    acc.y = fmaf(c, f0.y, acc.y);
    acc.z = fmaf(c, f1.x, acc.z);
    acc.w = fmaf(c, f1.y, acc.w);
}
__global__ void __launch_bounds__(256) gather_kernel(
    const int2* __restrict__ perm, const int* __restrict__ offs,
    const int* __restrict__ cnt, const __half* __restrict__ H,
    float* __restrict__ out) {
    int gid = blockIdx.x * 256 + threadIdx.x;
    int row = gid >> 5;
    if (row >= NROW) return;
    int lane = gid & 31;

    int v0, v1;
    if (row < NW) { v0 = row; v1 = -1; }
    else if (row < NW + NT) { int t = row - NW; v0 = NW + t; v1 = NW + NT + t; }
    else { int d = row - NW - NT; v0 = NW + 2 * NT + d; v1 = NW + 2 * NT + ND + d; }

    // hoist both segment descriptors (independent loads, issue together)
    int s0 = __ldg(offs + v0), n0 = __ldg(cnt + v0);
    int s1 = 0, n1 = 0;
    if (v1 >= 0) { s1 = __ldg(offs + v1); n1 = __ldg(cnt + v1); }

    float4 acc = make_float4(0.f, 0.f, 0.f, 0.f);
#pragma unroll
    for (int pass = 0; pass < 2; pass++) {
        int s = pass ? s1 : s0;
        int e = s + (pass ? n1 : n0);
        for (int i = s; i < e; i += 32) {
            int m = min(32, e - i);
            int2 md = (lane < m) ? __ldg(perm + i + lane) : make_int2(0, 0);
            int j = 0;
            for (; j + 1 < m; j += 2) {
                int   sA = __shfl_sync(0xffffffffu, md.x, j);
                float cA = __int_as_float(__shfl_sync(0xffffffffu, md.y, j));
                int   sB = __shfl_sync(0xffffffffu, md.x, j + 1);
                float cB = __int_as_float(__shfl_sync(0xffffffffu, md.y, j + 1));
                uint2 rA = __ldg((const uint2*)(H + (size_t)sA * D) + lane);
                uint2 rB = __ldg((const uint2*)(H + (size_t)sB * D) + lane);
                float2 a0 = __half22float2(*(__half2*)&rA.x);
                float2 a1 = __half22float2(*(__half2*)&rA.y);
                float2 b0 = __half22float2(*(__half2*)&rB.x);
                float2 b1 = __half22float2(*(__half2*)&rB.y);
                acc.x = fmaf(cA, a0.x, fmaf(cB, b0.x, acc.x));
                acc.y = fmaf(cA, a0.y, fmaf(cB, b0.y, acc.y));
                acc.z = fmaf(cA, a1.x, fmaf(cB, b1.x, acc.z));
                acc.w = fmaf(cA, a1.y, fmaf(cB, b1.y, acc.w));
            }
            if (j < m) {
                int   sA = __shfl_sync(0xffffffffu, md.x, j);
                float cA = __int_as_float(__shfl_sync(0xffffffffu, md.y, j));
                h_fma(acc, cA, H + (size_t)sA * D, lane);
            }
        }
    }
    float4 o = make_float4(fmaxf(acc.x, 0.f), fmaxf(acc.y, 0.f),
                           fmaxf(acc.z, 0.f), fmaxf(acc.w, 0.f));
    *(float4*)(out + (size_t)row * D + lane * 4) = o;
}

extern "C" void kernel_launch(void* const* d_in, const int* in_sizes, int n_in,
                              void* d_out, int out_size) {
    const float* h_word  = (const float*)d_in[0];
    const float* h_topic = (const float*)d_in[1];
    const float* W_ww = (const float*)d_in[3];
    const float* b_ww = (const float*)d_in[4];
    const float* W_wt = (const float*)d_in[5];
    const float* b_wt = (const float*)d_in[6];
    const float* W_wd = (const float*)d_in[7];
    const float* b_wd = (const float*)d_in[8];
    const float* W_td = (const float*)d_in[9];
    const float* b_td = (const float*)d_in[10];
    const float* W_tt = (const float*)d_in[11];
    const float* b_tt = (const float*)d_in[12];
    const int*   src_ww = (const int*)d_in[13];
    const int*   dst_ww = (const int*)d_in[14];
    const float* ew_ww  = (const float*)d_in[15];
    const int*   src_wt = (const int*)d_in[16];
    const int*   dst_wt = (const int*)d_in[17];
    const float* ew_wt  = (const float*)d_in[18];
    const int*   src_wd = (const int*)d_in[19];
    const int*   dst_wd = (const int*)d_in[20];
    const float* ew_wd  = (const float*)d_in[21];
    const int*   src_td = (const int*)d_in[22];
    const int*   dst_td = (const int*)d_in[23];
    const float* ew_td  = (const float*)d_in[24];
    const int*   src_tt = (const int*)d_in[25];
    const int*   dst_tt = (const int*)d_in[26];
    const float* ew_tt  = (const float*)d_in[27];

    const int E_ww = in_sizes[13];
    const int E_wt = in_sizes[16];
    const int E_wd = in_sizes[19];
    const int E_td = in_sizes[22];
    const int E_tt = in_sizes[25];

    float* out = (float*)d_out;

    __half* H;
    float* rcnt;
    int *cnt, *offs, *cursor, *bsum;
    int2* perm;
    cudaGetSymbolAddress((void**)&H, g_h);
    cudaGetSymbolAddress((void**)&cnt, g_cnt);
    cudaGetSymbolAddress((void**)&offs, g_offs);
    cudaGetSymbolAddress((void**)&cursor, g_cursor);
    cudaGetSymbolAddress((void**)&rcnt, g_rcnt);
    cudaGetSymbolAddress((void**)&bsum, g_bsum);
    cudaGetSymbolAddress((void**)&perm, g_perm);

    const int vb_ww = 0;
    const int vb_wt = NW;
    const int vb_tt = NW + NT;
    const int vb_wd = NW + 2 * NT;
    const int vb_td = NW + 2 * NT + ND;

    // fork/join resources (leaked on purpose; ~2 calls total, capture-safe)
    cudaStream_t s2;
    cudaEvent_t evFork, evJoin;
    cudaStreamCreateWithFlags(&s2, cudaStreamNonBlocking);
    cudaEventCreateWithFlags(&evFork, cudaEventDisableTiming);
    cudaEventCreateWithFlags(&evJoin, cudaEventDisableTiming);

    cudaEventRecord(evFork, 0);
    cudaStreamWaitEvent(s2, evFork, 0);

    // ---- side stream: compose -> GEMM ----
    {
        const int csm = (128 * 129 + 128) * (int)sizeof(float);
        cudaFuncSetAttribute(compose1, cudaFuncAttributeMaxDynamicSharedMemorySize, csm);
        cudaFuncSetAttribute(compose2, cudaFuncAttributeMaxDynamicSharedMemorySize, csm);
        compose1<<<258, 128, csm, s2>>>(W_ww, W_wt, b_ww, b_wt, W_td, W_tt, b_td, b_tt);
        compose2<<<129, 128, csm, s2>>>(W_wd, b_wd);
        const int smem_bytes = 139264;
        cudaFuncSetAttribute(gemm_mma, cudaFuncAttributeMaxDynamicSharedMemorySize,
                             smem_bytes);
        gemm_mma<<<TILES_W + TILES_T, 256, smem_bytes, s2>>>(h_word, h_topic, H);
        cudaEventRecord(evJoin, s2);
    }

    // ---- main stream: CSR build chain ----
    cudaMemsetAsync(cnt, 0, NV * sizeof(int), 0);
    {
        Cnt4Args ca;
        ca.dst4[0] = (const int4*)dst_ww; ca.vbase[0] = vb_ww;
        ca.dst4[1] = (const int4*)dst_wt; ca.vbase[1] = vb_wt;
        ca.dst4[2] = (const int4*)dst_tt; ca.vbase[2] = vb_tt;
        ca.dst4[3] = (const int4*)dst_wd; ca.vbase[3] = vb_wd;
        ca.dst4[4] = (const int4*)dst_td; ca.vbase[4] = vb_td;
        ca.cum4[0] = 0;
        ca.cum4[1] = E_ww / 4;
        ca.cum4[2] = ca.cum4[1] + E_wt / 4;
        ca.cum4[3] = ca.cum4[2] + E_tt / 4;
        ca.cum4[4] = ca.cum4[3] + E_wd / 4;
        ca.cum4[5] = ca.cum4[4] + E_td / 4;
        count_all<<<(ca.cum4[5] + 255) / 256, 256>>>(ca, cnt);
    }
    scanA<<<SCAN_BLK, 1024>>>(cnt, NV, offs, rcnt, bsum);
    scanC<<<SCAN_BLK, 1024>>>(offs, NV, bsum, cursor);
    {
        Fill4Args fa;
        fa.src4[0] = (const int4*)src_ww; fa.dst4[0] = (const int4*)dst_ww; fa.ew4[0] = (const float4*)ew_ww; fa.vbase[0] = vb_ww; fa.soff[0] = 0;
        fa.src4[1] = (const int4*)src_wt; fa.dst4[1] = (const int4*)dst_wt; fa.ew4[1] = (const float4*)ew_wt; fa.vbase[1] = vb_wt; fa.soff[1] = 0;
        fa.src4[2] = (const int4*)src_tt; fa.dst4[2] = (const int4*)dst_tt; fa.ew4[2] = (const float4*)ew_tt; fa.vbase[2] = vb_tt; fa.soff[2] = NW;
        fa.src4[3] = (const int4*)src_wd; fa.dst4[3] = (const int4*)dst_wd; fa.ew4[3] = (const float4*)ew_wd; fa.vbase[3] = vb_wd; fa.soff[3] = 0;
        fa.src4[4] = (const int4*)src_td; fa.dst4[4] = (const int4*)dst_td; fa.ew4[4] = (const float4*)ew_td; fa.vbase[4] = vb_td; fa.soff[4] = NW;
        fa.cum4[0] = 0;
        fa.cum4[1] = E_ww / 4;
        fa.cum4[2] = fa.cum4[1] + E_wt / 4;
        fa.cum4[3] = fa.cum4[2] + E_tt / 4;
        fa.cum4[4] = fa.cum4[3] + E_wd / 4;
        fa.cum4[5] = fa.cum4[4] + E_td / 4;
        fill_kernel<<<(fa.cum4[5] + 255) / 256, 256>>>(fa, rcnt, cursor, perm);
    }

    // join: gather needs both H (side) and CSR (main)
    cudaStreamWaitEvent(0, evJoin, 0);
    gather_kernel<<<(NROW * 32 + 255) / 256, 256>>>(perm, offs, cnt, H, out);
}

// round 10
// speedup vs baseline: 1.2527x; 1.0415x over previous
#include <cuda_runtime.h>
#include <cuda_bf16.h>
#include <cuda_fp16.h>
#include <cstdint>

#define D 128
#define NW 100000
#define NT 10000
#define ND 50000
#define NV (NW + NT + NT + ND + ND)   // 220000 virtual (relation,dst) nodes
#define NROW (NW + NT + ND)           // 160000 output rows
#define SCAN_BLK 54                   // ceil(NV/4096)
#define TILES_W 782                   // ceil(NW/128)
#define TILES_T 79                    // ceil(NT/128)

// ---------------- scratch (device globals: allocation-free) ----------------
__device__ __half g_h[(size_t)(NW + NT) * D];  // unified composed features, fp16
__device__ int   g_cntbuf[NV + SCAN_BLK];      // cnt [0,NV) + scan sentinel [NV,NV+54)
__device__ int   g_offs[NV];
__device__ int   g_cursor[NV];
__device__ float g_rcnt[NV];
__device__ int2  g_rowdesc[NROW];              // per output row: (start, len)
__device__ int2  g_perm[600000];
__device__ float g_T1[D * (D + 1)];
__device__ float g_bw[D];
__device__ float g_bt[D];
__device__ __nv_bfloat16 g_Bwh[D * D];
__device__ __nv_bfloat16 g_Bwl[D * D];
__device__ __nv_bfloat16 g_Bth[D * D];
__device__ __nv_bfloat16 g_Btl[D * D];

// ---------------- mma/ldmatrix helpers (plain PTX, sm_80+) ----------------
__device__ __forceinline__ uint32_t smem_u32(const void* p) {
    uint32_t a;
    asm("{ .reg .u64 t; cvta.to.shared.u64 t, %1; cvt.u32.u64 %0, t; }" : "=r"(a) : "l"(p));
    return a;
}
__device__ __forceinline__ void ldmx4(uint32_t* r, uint32_t addr) {
    asm volatile("ldmatrix.sync.aligned.m8n8.x4.shared.b16 {%0,%1,%2,%3}, [%4];"
                 : "=r"(r[0]), "=r"(r[1]), "=r"(r[2]), "=r"(r[3]) : "r"(addr));
}
#define MMA_BF16(c0, c1, c2, c3, a0, a1, a2, a3, b0, b1)                        \
    asm volatile(                                                               \
        "mma.sync.aligned.m16n8k16.row.col.f32.bf16.bf16.f32 "                  \
        "{%0,%1,%2,%3}, {%4,%5,%6,%7}, {%8,%9}, {%0,%1,%2,%3};"                 \
        : "+f"(c0), "+f"(c1), "+f"(c2), "+f"(c3)                                \
        : "r"(a0), "r"(a1), "r"(a2), "r"(a3), "r"(b0), "r"(b1))

// ---------------- weight composition ----------------
__global__ void __launch_bounds__(128) compose1(
    const float* __restrict__ Www, const float* __restrict__ Wwt,
    const float* __restrict__ bww, const float* __restrict__ bwt,
    const float* __restrict__ Wtd, const float* __restrict__ Wtt,
    const float* __restrict__ btd, const float* __restrict__ btt) {
    extern __shared__ float sm[];
    float* Ws = sm;
    float* Av = sm + 128 * 129;
    const int b = blockIdx.x;
    const int tid = threadIdx.x;
    const float* Wstage = (b < 129) ? Wwt : Wtt;
#pragma unroll 8
    for (int i = 0; i < 128; i++) Ws[i * 129 + tid] = Wstage[i * 128 + tid];
    if (b < 128)        Av[tid] = Www[tid * 128 + b];
    else if (b == 128)  Av[tid] = bww[tid];
    else if (b < 257)   Av[tid] = Wtd[tid * 128 + (b - 129)];
    else                Av[tid] = btd[tid];
    __syncthreads();
    float s = 0.f;
#pragma unroll 16
    for (int k = 0; k < 128; k++) s += Av[k] * Ws[tid * 129 + k];
    if (b < 128)        g_T1[b * 128 + tid] = s;
    else if (b == 128)  g_T1[128 * 128 + tid] = s + bwt[tid];
    else if (b < 257) {
        int k = b - 129;
        __nv_bfloat16 hh = __float2bfloat16(s);
        g_Bth[tid * 128 + k] = hh;
        g_Btl[tid * 128 + k] = __float2bfloat16(s - __bfloat162float(hh));
    } else              g_bt[tid] = s + btt[tid];
}
__global__ void __launch_bounds__(128) compose2(
    const float* __restrict__ Wwd, const float* __restrict__ bwd) {
    extern __shared__ float sm[];
    float* Ws = sm;
    float* Av = sm + 128 * 129;
    const int b = blockIdx.x;
    const int tid = threadIdx.x;
#pragma unroll 8
    for (int i = 0; i < 128; i++) Ws[i * 129 + tid] = Wwd[i * 128 + tid];
    Av[tid] = g_T1[b * 128 + tid];
    __syncthreads();
    float s = 0.f;
#pragma unroll 16
    for (int k = 0; k < 128; k++) s += Av[k] * Ws[tid * 129 + k];
    if (b < 128) {
        __nv_bfloat16 hh = __float2bfloat16(s);
        g_Bwh[tid * 128 + b] = hh;
        g_Bwl[tid * 128 + b] = __float2bfloat16(s - __bfloat162float(hh));
    } else g_bw[tid] = s + bwd[tid];
}

// ---------------- tensor-core GEMM: H[M,128] = A @ Bcomp^T + bias (fp16 out) ----
__global__ void __launch_bounds__(256, 1)
gemm_mma(const float* __restrict__ Aw, const float* __restrict__ At,
         __half* __restrict__ H) {
    extern __shared__ __align__(16) char smem[];
    __nv_bfloat16* As_hi = (__nv_bfloat16*)smem;                 // [128][136]
    __nv_bfloat16* As_lo = (__nv_bfloat16*)(smem + 34816);
    __nv_bfloat16* Bs_hi = (__nv_bfloat16*)(smem + 69632);
    __nv_bfloat16* Bs_lo = (__nv_bfloat16*)(smem + 104448);
    const int tid = threadIdx.x;
    const int wid = tid >> 5, lane = tid & 31;

    const float* A;
    const __nv_bfloat16 *Bh, *Bl;
    const float* bias;
    __half* C;
    int M, row0;
    if (blockIdx.x < TILES_W) {
        A = Aw; Bh = g_Bwh; Bl = g_Bwl; bias = g_bw; C = H;
        M = NW; row0 = blockIdx.x * 128;
    } else {
        A = At; Bh = g_Bth; Bl = g_Btl; bias = g_bt; C = H + (size_t)NW * D;
        M = NT; row0 = (blockIdx.x - TILES_W) * 128;
    }

    {
        const uint32_t* bh = (const uint32_t*)Bh;
        const uint32_t* bl = (const uint32_t*)Bl;
        uint32_t* dh = (uint32_t*)Bs_hi;
        uint32_t* dl = (uint32_t*)Bs_lo;
#pragma unroll
        for (int i = 0; i < 32; i++) {
            int idx = tid + 256 * i;
            int n = idx >> 6, w = idx & 63;
            dh[n * 68 + w] = __ldg(bh + idx);
            dl[n * 68 + w] = __ldg(bl + idx);
        }
    }
    {
#pragma unroll
        for (int i = 0; i < 16; i++) {
            int idx = tid + 256 * i;
            int r = idx >> 5, c4 = idx & 31;
            float4 f = (row0 + r < M)
                ? __ldg((const float4*)(A + (size_t)(row0 + r) * D) + c4)
                : make_float4(0.f, 0.f, 0.f, 0.f);
            __nv_bfloat16 h0 = __float2bfloat16(f.x), h1 = __float2bfloat16(f.y);
            __nv_bfloat16 h2 = __float2bfloat16(f.z), h3 = __float2bfloat16(f.w);
            __nv_bfloat162 ph0, ph1, pl0, pl1;
            ph0.x = h0; ph0.y = h1; ph1.x = h2; ph1.y = h3;
            pl0.x = __float2bfloat16(f.x - __bfloat162float(h0));
            pl0.y = __float2bfloat16(f.y - __bfloat162float(h1));
            pl1.x = __float2bfloat16(f.z - __bfloat162float(h2));
            pl1.y = __float2bfloat16(f.w - __bfloat162float(h3));
            int base = r * 136 + c4 * 4;
            *(__nv_bfloat162*)(As_hi + base)     = ph0;
            *(__nv_bfloat162*)(As_hi + base + 2) = ph1;
            *(__nv_bfloat162*)(As_lo + base)     = pl0;
            *(__nv_bfloat162*)(As_lo + base + 2) = pl1;
        }
    }
    __syncthreads();

    const uint32_t as_hi_b = smem_u32(As_hi), as_lo_b = smem_u32(As_lo);
    const uint32_t bs_hi_b = smem_u32(Bs_hi), bs_lo_b = smem_u32(Bs_lo);
    const int lr = lane & 7, lm = lane >> 3;

    uint32_t ah[8][4], al[8][4];
    {
        uint32_t arow = (uint32_t)(wid * 16 + lr + (lm & 1) * 8);
        uint32_t acol = (uint32_t)((lm >> 1) * 8);
        uint32_t abase = (arow * 136 + acol) * 2;
#pragma unroll
        for (int ks = 0; ks < 8; ks++) {
            ldmx4(ah[ks], as_hi_b + abase + ks * 32);
            ldmx4(al[ks], as_lo_b + abase + ks * 32);
        }
    }

    const int g = lane >> 2, t = lane & 3;
    const int orow0 = row0 + wid * 16 + g;
    const uint32_t bbase_sel = (lm >= 2) ? bs_lo_b : bs_hi_b;
    const uint32_t bcol = (uint32_t)((lm & 1) * 8);

#pragma unroll 4
    for (int nt = 0; nt < 16; nt++) {
        float c0 = 0.f, c1 = 0.f, c2 = 0.f, c3 = 0.f;
        uint32_t baddr = bbase_sel + (((uint32_t)(nt * 8 + lr)) * 136 + bcol) * 2;
#pragma unroll
        for (int ks = 0; ks < 8; ks++) {
            uint32_t b[4];
            ldmx4(b, baddr + ks * 32);
            MMA_BF16(c0, c1, c2, c3, ah[ks][0], ah[ks][1], ah[ks][2], ah[ks][3], b[0], b[1]);
            MMA_BF16(c0, c1, c2, c3, al[ks][0], al[ks][1], al[ks][2], al[ks][3], b[0], b[1]);
            MMA_BF16(c0, c1, c2, c3, ah[ks][0], ah[ks][1], ah[ks][2], ah[ks][3], b[2], b[3]);
        }
        int col = nt * 8 + t * 2;
        float2 b2 = __ldg((const float2*)(bias + col));
        if (orow0 < M)
            *(__half2*)(C + (size_t)orow0 * D + col) =
                __floats2half2_rn(c0 + b2.x, c1 + b2.y);
        if (orow0 + 8 < M)
            *(__half2*)(C + (size_t)(orow0 + 8) * D + col) =
                __floats2half2_rn(c2 + b2.x, c3 + b2.y);
    }
}

// ---------------- counts (int4 vectorized; row-interleaved vnode map) -------
struct Cnt4Args {
    const int4* dst4[5];
    int vbase[5];
    int vscale[5];
    int cum4[6];
};
__global__ void count_all(Cnt4Args a, int* __restrict__ cnt) {
    int g = blockIdx.x * blockDim.x + threadIdx.x;
    if (g >= a.cum4[5]) return;
    int r = 0;
    while (g >= a.cum4[r + 1]) r++;
    int4 d = __ldcs(a.dst4[r] + (g - a.cum4[r]));
    const int vb = a.vbase[r], vs = a.vscale[r];
    atomicAdd(cnt + vb + d.x * vs, 1);
    atomicAdd(cnt + vb + d.y * vs, 1);
    atomicAdd(cnt + vb + d.z * vs, 1);
    atomicAdd(cnt + vb + d.w * vs, 1);
}

// ---------------- single-pass scan (decoupled lookback; 54 blocks resident) --
__global__ void __launch_bounds__(1024) scan_all(
    const int* __restrict__ cnt, int n,
    int* __restrict__ offs, float* __restrict__ rcnt,
    int* __restrict__ cursor, int* __restrict__ bsumZ) {
    __shared__ int wsum[32];
    __shared__ int pref;
    const int tid = threadIdx.x;
    const int bid = blockIdx.x;
    const int base = bid * 4096 + tid * 4;
    int v[4];
#pragma unroll
    for (int k = 0; k < 4; k++) v[k] = (base + k < n) ? cnt[base + k] : 0;
#pragma unroll
    for (int k = 0; k < 4; k++)
        if (base + k < n) rcnt[base + k] = 1.0f / (float)max(v[k], 1);
    int t = v[0] + v[1] + v[2] + v[3];
    const int lane = tid & 31, w = tid >> 5;
    int inc = t;
#pragma unroll
    for (int dlt = 1; dlt < 32; dlt <<= 1) {
        int x = __shfl_up_sync(0xffffffffu, inc, dlt);
        if (lane >= dlt) inc += x;
    }
    if (lane == 31) wsum[w] = inc;
    __syncthreads();
    if (w == 0) {
        int si = wsum[lane];
#pragma unroll
        for (int dlt = 1; dlt < 32; dlt <<= 1) {
            int x = __shfl_up_sync(0xffffffffu, si, dlt);
            if (lane >= dlt) si += x;
        }
        wsum[lane] = si;
    }
    __syncthreads();
    // publish aggregate (value+1 sentinel; buffer pre-zeroed by memset)
    if (tid == 0) {
        __threadfence();
        atomicExch(bsumZ + bid, wsum[31] + 1);
    }
    // lookback: sum predecessors' aggregates (all blocks resident: no deadlock)
    if (tid < 32) {
        int acc = 0;
        for (int p = lane; p < bid; p += 32) {
            int x;
            do { x = atomicAdd(bsumZ + p, 0); } while (x == 0);
            acc += x - 1;
        }
#pragma unroll
        for (int dlt = 16; dlt > 0; dlt >>= 1)
            acc += __shfl_down_sync(0xffffffffu, acc, dlt);
        if (lane == 0) pref = acc;
    }
    __syncthreads();
    int o = pref + inc - t + (w > 0 ? wsum[w - 1] : 0);
#pragma unroll
    for (int k = 0; k < 4; k++) {
        if (base + k < n) { offs[base + k] = o; cursor[base + k] = o; }
        o += v[k];
    }
}

// ---------------- rowdesc: per output row (start, len) ----------------------
__global__ void rowdesc_kernel(const int* __restrict__ offs,
                               const int* __restrict__ cnt,
                               int2* __restrict__ rd) {
    int row = blockIdx.x * blockDim.x + threadIdx.x;
    if (row >= NROW) return;
    int v;
    if (row < NW) {
        rd[row] = make_int2(offs[row], cnt[row]);
        return;
    } else if (row < NW + NT) {
        v = NW + 2 * (row - NW);
    } else {
        v = NW + 2 * NT + 2 * (row - NW - NT);
    }
    // adjacent vnodes -> contiguous CSR segments -> single merged segment
    rd[row] = make_int2(offs[v], cnt[v] + cnt[v + 1]);
}

// ---------------- CSR fill (4 edges/thread, row-interleaved vnode map) ------
struct Fill4Args {
    const int4*   src4[5];
    const int4*   dst4[5];
    const float4* ew4[5];
    int vbase[5];
    int vscale[5];
    int soff[5];
    int cum4[6];
};
__global__ void fill_kernel(Fill4Args a, const float* __restrict__ rcnt,
                            int* __restrict__ cursor, int2* __restrict__ perm) {
    int g = blockIdx.x * blockDim.x + threadIdx.x;
    if (g >= a.cum4[5]) return;
    int r = 0;
    while (g >= a.cum4[r + 1]) r++;
    int e4 = g - a.cum4[r];
    int4   s = __ldcs(a.src4[r] + e4);
    int4   d = __ldcs(a.dst4[r] + e4);
    float4 w = __ldcs(a.ew4[r] + e4);
    const int vb = a.vbase[r], vs = a.vscale[r], so = a.soff[r];
    {
        int v = vb + d.x * vs;
        int pos = atomicAdd(cursor + v, 1);
        perm[pos] = make_int2(s.x + so, __float_as_int(w.x * __ldg(rcnt + v)));
    }
    {
        int v = vb + d.y * vs;
        int pos = atomicAdd(cursor + v, 1);
        perm[pos] = make_int2(s.y + so, __float_as_int(w.y * __ldg(rcnt + v)));
    }
    {
        int v = vb + d.z * vs;
        int pos = atomicAdd(cursor + v, 1);
        perm[pos] = make_int2(s.z + so, __float_as_int(w.z * __ldg(rcnt + v)));
    }
    {
        int v = vb + d.w * vs;
        int pos = atomicAdd(cursor + v, 1);
        perm[pos] = make_int2(s.w + so, __float_as_int(w.w * __ldg(rcnt + v)));
    }
}

// ---------------- gather: one warp/row, single merged segment, fused relu ---
__global__ void __launch_bounds__(256) gather_kernel(
    const int2* __restrict__ perm, const int2* __restrict__ rowdesc,
    const __half* __restrict__ H, float* __restrict__ out) {
    int gid = blockIdx.x * 256 + threadIdx.x;
    int row = gid >> 5;
    if (row >= NROW) return;
    int lane = gid & 31;

    int2 seg = __ldg(rowdesc + row);   // broadcast: one transaction per warp
    const int s = seg.x, e = seg.x + seg.y;

    float4 acc = make_float4(0.f, 0.f, 0.f, 0.f);
    for (int i = s; i < e; i += 32) {
        int m = min(32, e - i);
        int2 md = (lane < m) ? __ldg(perm + i + lane) : make_int2(0, 0);
        int j = 0;
        for (; j + 1 < m; j += 2) {
            int   sA = __shfl_sync(0xffffffffu, md.x, j);
            float cA = __int_as_float(__shfl_sync(0xffffffffu, md.y, j));
            int   sB = __shfl_sync(0xffffffffu, md.x, j + 1);
            float cB = __int_as_float(__shfl_sync(0xffffffffu, md.y, j + 1));
            uint2 rA = __ldg((const uint2*)(H + (size_t)sA * D) + lane);
            uint2 rB = __ldg((const uint2*)(H + (size_t)sB * D) + lane);
            float2 a0 = __half22float2(*(__half2*)&rA.x);
            float2 a1 = __half22float2(*(__half2*)&rA.y);
            float2 b0 = __half22float2(*(__half2*)&rB.x);
            float2 b1 = __half22float2(*(__half2*)&rB.y);
            acc.x = fmaf(cA, a0.x, fmaf(cB, b0.x, acc.x));
            acc.y = fmaf(cA, a0.y, fmaf(cB, b0.y, acc.y));
            acc.z = fmaf(cA, a1.x, fmaf(cB, b1.x, acc.z));
            acc.w = fmaf(cA, a1.y, fmaf(cB, b1.y, acc.w));
        }
        if (j < m) {
            int   sA = __shfl_sync(0xffffffffu, md.x, j);
            float cA = __int_as_float(__shfl_sync(0xffffffffu, md.y, j));
            uint2 rA = __ldg((const uint2*)(H + (size_t)sA * D) + lane);
            float2 a0 = __half22float2(*(__half2*)&rA.x);
            float2 a1 = __half22float2(*(__half2*)&rA.y);
            acc.x = fmaf(cA, a0.x, acc.x);
            acc.y = fmaf(cA, a0.y, acc.y);
            acc.z = fmaf(cA, a1.x, acc.z);
            acc.w = fmaf(cA, a1.y, acc.w);
        }
    }
    float4 o = make_float4(fmaxf(acc.x, 0.f), fmaxf(acc.y, 0.f),
                           fmaxf(acc.z, 0.f), fmaxf(acc.w, 0.f));
    *(float4*)(out + (size_t)row * D + lane * 4) = o;
}

extern "C" void kernel_launch(void* const* d_in, const int* in_sizes, int n_in,
                              void* d_out, int out_size) {
    const float* h_word  = (const float*)d_in[0];
    const float* h_topic = (const float*)d_in[1];
    const float* W_ww = (const float*)d_in[3];
    const float* b_ww = (const float*)d_in[4];
    const float* W_wt = (const float*)d_in[5];
    const float* b_wt = (const float*)d_in[6];
    const float* W_wd = (const float*)d_in[7];
    const float* b_wd = (const float*)d_in[8];
    const float* W_td = (const float*)d_in[9];
    const float* b_td = (const float*)d_in[10];
    const float* W_tt = (const float*)d_in[11];
    const float* b_tt = (const float*)d_in[12];
    const int*   src_ww = (const int*)d_in[13];
    const int*   dst_ww = (const int*)d_in[14];
    const float* ew_ww  = (const float*)d_in[15];
    const int*   src_wt = (const int*)d_in[16];
    const int*   dst_wt = (const int*)d_in[17];
    const float* ew_wt  = (const float*)d_in[18];
    const int*   src_wd = (const int*)d_in[19];
    const int*   dst_wd = (const int*)d_in[20];
    const float* ew_wd  = (const float*)d_in[21];
    const int*   src_td = (const int*)d_in[22];
    const int*   dst_td = (const int*)d_in[23];
    const float* ew_td  = (const float*)d_in[24];
    const int*   src_tt = (const int*)d_in[25];
    const int*   dst_tt = (const int*)d_in[26];
    const float* ew_tt  = (const float*)d_in[27];

    const int E_ww = in_sizes[13];
    const int E_wt = in_sizes[16];
    const int E_wd = in_sizes[19];
    const int E_td = in_sizes[22];
    const int E_tt = in_sizes[25];

    float* out = (float*)d_out;

    __half* H;
    float* rcnt;
    int *cntbuf, *offs, *cursor;
    int2 *perm, *rowdesc;
    cudaGetSymbolAddress((void**)&H, g_h);
    cudaGetSymbolAddress((void**)&cntbuf, g_cntbuf);
    cudaGetSymbolAddress((void**)&offs, g_offs);
    cudaGetSymbolAddress((void**)&cursor, g_cursor);
    cudaGetSymbolAddress((void**)&rcnt, g_rcnt);
    cudaGetSymbolAddress((void**)&perm, g_perm);
    cudaGetSymbolAddress((void**)&rowdesc, g_rowdesc);
    int* cnt = cntbuf;
    int* bsumZ = cntbuf + NV;

    // row-interleaved vnode map: ww -> [0,NW); wt/tt -> NW+2t / NW+2t+1;
    // wd/td -> NW+2NT+2d / NW+2NT+2d+1
    const int VB_WW = 0,        VS_WW = 1;
    const int VB_WT = NW,       VS_WT = 2;
    const int VB_TT = NW + 1,   VS_TT = 2;
    const int VB_WD = NW + 2 * NT,     VS_WD = 2;
    const int VB_TD = NW + 2 * NT + 1, VS_TD = 2;

    // fork/join resources (leaked on purpose; ~2 calls total, capture-safe)
    cudaStream_t s2;
    cudaEvent_t evFork, evJoin;
    cudaStreamCreateWithFlags(&s2, cudaStreamNonBlocking);
    cudaEventCreateWithFlags(&evFork, cudaEventDisableTiming);
    cudaEventCreateWithFlags(&evJoin, cudaEventDisableTiming);

    cudaEventRecord(evFork, 0);
    cudaStreamWaitEvent(s2, evFork, 0);

    // ---- side stream: compose -> GEMM ----
    {
        const int csm = (128 * 129 + 128) * (int)sizeof(float);
        cudaFuncSetAttribute(compose1, cudaFuncAttributeMaxDynamicSharedMemorySize, csm);
        cudaFuncSetAttribute(compose2, cudaFuncAttributeMaxDynamicSharedMemorySize, csm);
        compose1<<<258, 128, csm, s2>>>(W_ww, W_wt, b_ww, b_wt, W_td, W_tt, b_td, b_tt);
        compose2<<<129, 128, csm, s2>>>(W_wd, b_wd);
        const int smem_bytes = 139264;
        cudaFuncSetAttribute(gemm_mma, cudaFuncAttributeMaxDynamicSharedMemorySize,
                             smem_bytes);
        gemm_mma<<<TILES_W + TILES_T, 256, smem_bytes, s2>>>(h_word, h_topic, H);
        cudaEventRecord(evJoin, s2);
    }

    // ---- main stream: CSR build chain ----
    cudaMemsetAsync(cntbuf, 0, (NV + SCAN_BLK) * sizeof(int), 0);
    {
        Cnt4Args ca;
        ca.dst4[0] = (const int4*)dst_ww; ca.vbase[0] = VB_WW; ca.vscale[0] = VS_WW;
        ca.dst4[1] = (const int4*)dst_wt; ca.vbase[1] = VB_WT; ca.vscale[1] = VS_WT;
        ca.dst4[2] = (const int4*)dst_tt; ca.vbase[2] = VB_TT; ca.vscale[2] = VS_TT;
        ca.dst4[3] = (const int4*)dst_wd; ca.vbase[3] = VB_WD; ca.vscale[3] = VS_WD;
        ca.dst4[4] = (const int4*)dst_td; ca.vbase[4] = VB_TD; ca.vscale[4] = VS_TD;
        ca.cum4[0] = 0;
        ca.cum4[1] = E_ww / 4;
        ca.cum4[2] = ca.cum4[1] + E_wt / 4;
        ca.cum4[3] = ca.cum4[2] + E_tt / 4;
        ca.cum4[4] = ca.cum4[3] + E_wd / 4;
        ca.cum4[5] = ca.cum4[4] + E_td / 4;
        count_all<<<(ca.cum4[5] + 255) / 256, 256>>>(ca, cnt);
    }
    scan_all<<<SCAN_BLK, 1024>>>(cnt, NV, offs, rcnt, cursor, bsumZ);
    rowdesc_kernel<<<(NROW + 255) / 256, 256>>>(offs, cnt, rowdesc);
    {
        Fill4Args fa;
        fa.src4[0] = (const int4*)src_ww; fa.dst4[0] = (const int4*)dst_ww; fa.ew4[0] = (const float4*)ew_ww; fa.vbase[0] = VB_WW; fa.vscale[0] = VS_WW; fa.soff[0] = 0;
        fa.src4[1] = (const int4*)src_wt; fa.dst4[1] = (const int4*)dst_wt; fa.ew4[1] = (const float4*)ew_wt; fa.vbase[1] = VB_WT; fa.vscale[1] = VS_WT; fa.soff[1] = 0;
        fa.src4[2] = (const int4*)src_tt; fa.dst4[2] = (const int4*)dst_tt; fa.ew4[2] = (const float4*)ew_tt; fa.vbase[2] = VB_TT; fa.vscale[2] = VS_TT; fa.soff[2] = NW;
        fa.src4[3] = (const int4*)src_wd; fa.dst4[3] = (const int4*)dst_wd; fa.ew4[3] = (const float4*)ew_wd; fa.vbase[3] = VB_WD; fa.vscale[3] = VS_WD; fa.soff[3] = 0;
        fa.src4[4] = (const int4*)src_td; fa.dst4[4] = (const int4*)dst_td; fa.ew4[4] = (const float4*)ew_td; fa.vbase[4] = VB_TD; fa.vscale[4] = VS_TD; fa.soff[4] = NW;
        fa.cum4[0] = 0;
        fa.cum4[1] = E_ww / 4;
        fa.cum4[2] = fa.cum4[1] + E_wt / 4;
        fa.cum4[3] = fa.cum4[2] + E_tt / 4;
        fa.cum4[4] = fa.cum4[3] + E_wd / 4;
        fa.cum4[5] = fa.cum4[4] + E_td / 4;
        fill_kernel<<<(fa.cum4[5] + 255) / 256, 256>>>(fa, rcnt, cursor, perm);
    }

    // join: gather needs both H (side) and CSR (main)
    cudaStreamWaitEvent(0, evJoin, 0);
    gather_kernel<<<(NROW * 32 + 255) / 256, 256>>>(perm, rowdesc, H, out);
}

// round 11
// speedup vs baseline: 1.2849x; 1.0257x over previous
#include <cuda_runtime.h>
#include <cuda_bf16.h>
#include <cuda_fp16.h>
#include <cstdint>

#define D 128
#define NW 100000
#define NT 10000
#define ND 50000
#define NV (NW + NT + NT + ND + ND)   // 220000 virtual (relation,dst) nodes
#define NROW (NW + NT + ND)           // 160000 output rows
#define SCAN_BLK 54                   // ceil(NV/4096)
#define TILES_W 782                   // ceil(NW/128)
#define TILES_T 79                    // ceil(NT/128)

// ---------------- scratch (device globals: allocation-free) ----------------
__device__ __half g_h[(size_t)(NW + NT) * D];  // unified composed features, fp16
__device__ int   g_cntbuf[NV + SCAN_BLK];      // cnt [0,NV) + scan sentinel
__device__ int   g_offs[NV];
__device__ int   g_cursor[NV];
__device__ float g_rcnt[NV];
__device__ int2  g_rowdesc[NROW];              // per output row: (start, len)
__device__ int2  g_perm[600000];
__device__ float g_T1[D * (D + 1)];
__device__ float g_bw[D];
__device__ float g_bt[D];
__device__ __nv_bfloat16 g_Bwh[D * D];
__device__ __nv_bfloat16 g_Bwl[D * D];
__device__ __nv_bfloat16 g_Bth[D * D];
__device__ __nv_bfloat16 g_Btl[D * D];

// ---------------- mma/ldmatrix helpers (plain PTX, sm_80+) ----------------
__device__ __forceinline__ uint32_t smem_u32(const void* p) {
    uint32_t a;
    asm("{ .reg .u64 t; cvta.to.shared.u64 t, %1; cvt.u32.u64 %0, t; }" : "=r"(a) : "l"(p));
    return a;
}
__device__ __forceinline__ void ldmx4(uint32_t* r, uint32_t addr) {
    asm volatile("ldmatrix.sync.aligned.m8n8.x4.shared.b16 {%0,%1,%2,%3}, [%4];"
                 : "=r"(r[0]), "=r"(r[1]), "=r"(r[2]), "=r"(r[3]) : "r"(addr));
}
#define MMA_BF16(c0, c1, c2, c3, a0, a1, a2, a3, b0, b1)                        \
    asm volatile(                                                               \
        "mma.sync.aligned.m16n8k16.row.col.f32.bf16.bf16.f32 "                  \
        "{%0,%1,%2,%3}, {%4,%5,%6,%7}, {%8,%9}, {%0,%1,%2,%3};"                 \
        : "+f"(c0), "+f"(c1), "+f"(c2), "+f"(c3)                                \
        : "r"(a0), "r"(a1), "r"(a2), "r"(a3), "r"(b0), "r"(b1))

// ---------------- weight composition ----------------
__global__ void __launch_bounds__(128) compose1(
    const float* __restrict__ Www, const float* __restrict__ Wwt,
    const float* __restrict__ bww, const float* __restrict__ bwt,
    const float* __restrict__ Wtd, const float* __restrict__ Wtt,
    const float* __restrict__ btd, const float* __restrict__ btt) {
    extern __shared__ float sm[];
    float* Ws = sm;
    float* Av = sm + 128 * 129;
    const int b = blockIdx.x;
    const int tid = threadIdx.x;
    const float* Wstage = (b < 129) ? Wwt : Wtt;
#pragma unroll 8
    for (int i = 0; i < 128; i++) Ws[i * 129 + tid] = Wstage[i * 128 + tid];
    if (b < 128)        Av[tid] = Www[tid * 128 + b];
    else if (b == 128)  Av[tid] = bww[tid];
    else if (b < 257)   Av[tid] = Wtd[tid * 128 + (b - 129)];
    else                Av[tid] = btd[tid];
    __syncthreads();
    float s = 0.f;
#pragma unroll 16
    for (int k = 0; k < 128; k++) s += Av[k] * Ws[tid * 129 + k];
    if (b < 128)        g_T1[b * 128 + tid] = s;
    else if (b == 128)  g_T1[128 * 128 + tid] = s + bwt[tid];
    else if (b < 257) {
        int k = b - 129;
        __nv_bfloat16 hh = __float2bfloat16(s);
        g_Bth[tid * 128 + k] = hh;
        g_Btl[tid * 128 + k] = __float2bfloat16(s - __bfloat162float(hh));
    } else              g_bt[tid] = s + btt[tid];
}
__global__ void __launch_bounds__(128) compose2(
    const float* __restrict__ Wwd, const float* __restrict__ bwd) {
    extern __shared__ float sm[];
    float* Ws = sm;
    float* Av = sm + 128 * 129;
    const int b = blockIdx.x;
    const int tid = threadIdx.x;
#pragma unroll 8
    for (int i = 0; i < 128; i++) Ws[i * 129 + tid] = Wwd[i * 128 + tid];
    Av[tid] = g_T1[b * 128 + tid];
    __syncthreads();
    float s = 0.f;
#pragma unroll 16
    for (int k = 0; k < 128; k++) s += Av[k] * Ws[tid * 129 + k];
    if (b < 128) {
        __nv_bfloat16 hh = __float2bfloat16(s);
        g_Bwh[tid * 128 + b] = hh;
        g_Bwl[tid * 128 + b] = __float2bfloat16(s - __bfloat162float(hh));
    } else g_bw[tid] = s + bwd[tid];
}

// ---------------- tensor-core GEMM: H[M,128] = A @ Bcomp^T + bias (fp16 out) ----
__global__ void __launch_bounds__(256, 1)
gemm_mma(const float* __restrict__ Aw, const float* __restrict__ At,
         __half* __restrict__ H) {
    extern __shared__ __align__(16) char smem[];
    __nv_bfloat16* As_hi = (__nv_bfloat16*)smem;                 // [128][136]
    __nv_bfloat16* As_lo = (__nv_bfloat16*)(smem + 34816);
    __nv_bfloat16* Bs_hi = (__nv_bfloat16*)(smem + 69632);
    __nv_bfloat16* Bs_lo = (__nv_bfloat16*)(smem + 104448);
    const int tid = threadIdx.x;
    const int wid = tid >> 5, lane = tid & 31;

    const float* A;
    const __nv_bfloat16 *Bh, *Bl;
    const float* bias;
    __half* C;
    int M, row0;
    if (blockIdx.x < TILES_W) {
        A = Aw; Bh = g_Bwh; Bl = g_Bwl; bias = g_bw; C = H;
        M = NW; row0 = blockIdx.x * 128;
    } else {
        A = At; Bh = g_Bth; Bl = g_Btl; bias = g_bt; C = H + (size_t)NW * D;
        M = NT; row0 = (blockIdx.x - TILES_W) * 128;
    }

    {
        const uint32_t* bh = (const uint32_t*)Bh;
        const uint32_t* bl = (const uint32_t*)Bl;
        uint32_t* dh = (uint32_t*)Bs_hi;
        uint32_t* dl = (uint32_t*)Bs_lo;
#pragma unroll
        for (int i = 0; i < 32; i++) {
            int idx = tid + 256 * i;
            int n = idx >> 6, w = idx & 63;
            dh[n * 68 + w] = __ldg(bh + idx);
            dl[n * 68 + w] = __ldg(bl + idx);
        }
    }
    {
#pragma unroll
        for (int i = 0; i < 16; i++) {
            int idx = tid + 256 * i;
            int r = idx >> 5, c4 = idx & 31;
            float4 f = (row0 + r < M)
                ? __ldg((const float4*)(A + (size_t)(row0 + r) * D) + c4)
                : make_float4(0.f, 0.f, 0.f, 0.f);
            __nv_bfloat16 h0 = __float2bfloat16(f.x), h1 = __float2bfloat16(f.y);
            __nv_bfloat16 h2 = __float2bfloat16(f.z), h3 = __float2bfloat16(f.w);
            __nv_bfloat162 ph0, ph1, pl0, pl1;
            ph0.x = h0; ph0.y = h1; ph1.x = h2; ph1.y = h3;
            pl0.x = __float2bfloat16(f.x - __bfloat162float(h0));
            pl0.y = __float2bfloat16(f.y - __bfloat162float(h1));
            pl1.x = __float2bfloat16(f.z - __bfloat162float(h2));
            pl1.y = __float2bfloat16(f.w - __bfloat162float(h3));
            int base = r * 136 + c4 * 4;
            *(__nv_bfloat162*)(As_hi + base)     = ph0;
            *(__nv_bfloat162*)(As_hi + base + 2) = ph1;
            *(__nv_bfloat162*)(As_lo + base)     = pl0;
            *(__nv_bfloat162*)(As_lo + base + 2) = pl1;
        }
    }
    __syncthreads();

    const uint32_t as_hi_b = smem_u32(As_hi), as_lo_b = smem_u32(As_lo);
    const uint32_t bs_hi_b = smem_u32(Bs_hi), bs_lo_b = smem_u32(Bs_lo);
    const int lr = lane & 7, lm = lane >> 3;

    uint32_t ah[8][4], al[8][4];
    {
        uint32_t arow = (uint32_t)(wid * 16 + lr + (lm & 1) * 8);
        uint32_t acol = (uint32_t)((lm >> 1) * 8);
        uint32_t abase = (arow * 136 + acol) * 2;
#pragma unroll
        for (int ks = 0; ks < 8; ks++) {
            ldmx4(ah[ks], as_hi_b + abase + ks * 32);
            ldmx4(al[ks], as_lo_b + abase + ks * 32);
        }
    }

    const int g = lane >> 2, t = lane & 3;
    const int orow0 = row0 + wid * 16 + g;
    const uint32_t bbase_sel = (lm >= 2) ? bs_lo_b : bs_hi_b;
    const uint32_t bcol = (uint32_t)((lm & 1) * 8);

#pragma unroll 4
    for (int nt = 0; nt < 16; nt++) {
        float c0 = 0.f, c1 = 0.f, c2 = 0.f, c3 = 0.f;
        uint32_t baddr = bbase_sel + (((uint32_t)(nt * 8 + lr)) * 136 + bcol) * 2;
#pragma unroll
        for (int ks = 0; ks < 8; ks++) {
            uint32_t b[4];
            ldmx4(b, baddr + ks * 32);
            MMA_BF16(c0, c1, c2, c3, ah[ks][0], ah[ks][1], ah[ks][2], ah[ks][3], b[0], b[1]);
            MMA_BF16(c0, c1, c2, c3, al[ks][0], al[ks][1], al[ks][2], al[ks][3], b[0], b[1]);
            MMA_BF16(c0, c1, c2, c3, ah[ks][0], ah[ks][1], ah[ks][2], ah[ks][3], b[2], b[3]);
        }
        int col = nt * 8 + t * 2;
        float2 b2 = __ldg((const float2*)(bias + col));
        if (orow0 < M)
            *(__half2*)(C + (size_t)orow0 * D + col) =
                __floats2half2_rn(c0 + b2.x, c1 + b2.y);
        if (orow0 + 8 < M)
            *(__half2*)(C + (size_t)(orow0 + 8) * D + col) =
                __floats2half2_rn(c2 + b2.x, c3 + b2.y);
    }
}

// ---------------- counts (int4 vectorized; row-interleaved vnode map) -------
struct Cnt4Args {
    const int4* dst4[5];
    int vbase[5];
    int vscale[5];
    int cum4[6];
};
__global__ void count_all(Cnt4Args a, int* __restrict__ cnt) {
    int g = blockIdx.x * blockDim.x + threadIdx.x;
    if (g >= a.cum4[5]) return;
    int r = 0;
    while (g >= a.cum4[r + 1]) r++;
    int4 d = __ldcs(a.dst4[r] + (g - a.cum4[r]));
    const int vb = a.vbase[r], vs = a.vscale[r];
    atomicAdd(cnt + vb + d.x * vs, 1);
    atomicAdd(cnt + vb + d.y * vs, 1);
    atomicAdd(cnt + vb + d.z * vs, 1);
    atomicAdd(cnt + vb + d.w * vs, 1);
}

// ---------------- single-pass scan (decoupled lookback; 54 blocks resident) --
__global__ void __launch_bounds__(1024) scan_all(
    const int* __restrict__ cnt, int n,
    int* __restrict__ offs, float* __restrict__ rcnt,
    int* __restrict__ cursor, int* __restrict__ bsumZ) {
    __shared__ int wsum[32];
    __shared__ int pref;
    const int tid = threadIdx.x;
    const int bid = blockIdx.x;
    const int base = bid * 4096 + tid * 4;
    int v[4];
#pragma unroll
    for (int k = 0; k < 4; k++) v[k] = (base + k < n) ? cnt[base + k] : 0;
#pragma unroll
    for (int k = 0; k < 4; k++)
        if (base + k < n) rcnt[base + k] = 1.0f / (float)max(v[k], 1);
    int t = v[0] + v[1] + v[2] + v[3];
    const int lane = tid & 31, w = tid >> 5;
    int inc = t;
#pragma unroll
    for (int dlt = 1; dlt < 32; dlt <<= 1) {
        int x = __shfl_up_sync(0xffffffffu, inc, dlt);
        if (lane >= dlt) inc += x;
    }
    if (lane == 31) wsum[w] = inc;
    __syncthreads();
    if (w == 0) {
        int si = wsum[lane];
#pragma unroll
        for (int dlt = 1; dlt < 32; dlt <<= 1) {
            int x = __shfl_up_sync(0xffffffffu, si, dlt);
            if (lane >= dlt) si += x;
        }
        wsum[lane] = si;
    }
    __syncthreads();
    if (tid == 0) {
        __threadfence();
        atomicExch(bsumZ + bid, wsum[31] + 1);
    }
    if (tid < 32) {
        int acc = 0;
        for (int p = lane; p < bid; p += 32) {
            int x;
            do { x = atomicAdd(bsumZ + p, 0); } while (x == 0);
            acc += x - 1;
        }
#pragma unroll
        for (int dlt = 16; dlt > 0; dlt >>= 1)
            acc += __shfl_down_sync(0xffffffffu, acc, dlt);
        if (lane == 0) pref = acc;
    }
    __syncthreads();
    int o = pref + inc - t + (w > 0 ? wsum[w - 1] : 0);
#pragma unroll
    for (int k = 0; k < 4; k++) {
        if (base + k < n) { offs[base + k] = o; cursor[base + k] = o; }
        o += v[k];
    }
}

// ---------------- rowdesc: per output row (start, len) ----------------------
__global__ void rowdesc_kernel(const int* __restrict__ offs,
                               const int* __restrict__ cnt,
                               int2* __restrict__ rd) {
    int row = blockIdx.x * blockDim.x + threadIdx.x;
    if (row >= NROW) return;
    int v;
    if (row < NW) {
        rd[row] = make_int2(offs[row], cnt[row]);
        return;
    } else if (row < NW + NT) {
        v = NW + 2 * (row - NW);
    } else {
        v = NW + 2 * NT + 2 * (row - NW - NT);
    }
    rd[row] = make_int2(offs[v], cnt[v] + cnt[v + 1]);
}

// ---------------- CSR fill (4 edges/thread, row-interleaved vnode map) ------
struct Fill4Args {
    const int4*   src4[5];
    const int4*   dst4[5];
    const float4* ew4[5];
    int vbase[5];
    int vscale[5];
    int soff[5];
    int cum4[6];
};
__global__ void fill_kernel(Fill4Args a, const float* __restrict__ rcnt,
                            int* __restrict__ cursor, int2* __restrict__ perm) {
    int g = blockIdx.x * blockDim.x + threadIdx.x;
    if (g >= a.cum4[5]) return;
    int r = 0;
    while (g >= a.cum4[r + 1]) r++;
    int e4 = g - a.cum4[r];
    int4   s = __ldcs(a.src4[r] + e4);
    int4   d = __ldcs(a.dst4[r] + e4);
    float4 w = __ldcs(a.ew4[r] + e4);
    const int vb = a.vbase[r], vs = a.vscale[r], so = a.soff[r];
    {
        int v = vb + d.x * vs;
        int pos = atomicAdd(cursor + v, 1);
        perm[pos] = make_int2(s.x + so, __float_as_int(w.x * __ldg(rcnt + v)));
    }
    {
        int v = vb + d.y * vs;
        int pos = atomicAdd(cursor + v, 1);
        perm[pos] = make_int2(s.y + so, __float_as_int(w.y * __ldg(rcnt + v)));
    }
    {
        int v = vb + d.z * vs;
        int pos = atomicAdd(cursor + v, 1);
        perm[pos] = make_int2(s.z + so, __float_as_int(w.z * __ldg(rcnt + v)));
    }
    {
        int v = vb + d.w * vs;
        int pos = atomicAdd(cursor + v, 1);
        perm[pos] = make_int2(s.w + so, __float_as_int(w.w * __ldg(rcnt + v)));
    }
}

// ---------------- gather v3: shuffle-free, uniform broadcast perm loads -----
// One warp per row; per 4-edge group: 4 independent uniform perm loads (L2
// broadcast, 1 transaction each) -> 4 independent H-row loads (MLP=4).
// Group tail padded with coef=0 entries (points at a valid row; fma adds 0).
__global__ void __launch_bounds__(256) gather_kernel(
    const int2* __restrict__ perm, const int2* __restrict__ rowdesc,
    const __half* __restrict__ H, float* __restrict__ out) {
    int gid = blockIdx.x * 256 + threadIdx.x;
    int row = gid >> 5;
    if (row >= NROW) return;
    int lane = gid & 31;

    int2 seg = __ldg(rowdesc + row);
    const int s = seg.x, e = seg.x + seg.y;

    float4 acc = make_float4(0.f, 0.f, 0.f, 0.f);
    for (int i = s; i < e; i += 4) {
        const int rem = e - i;
        int2 m0 = __ldg(perm + i);
        int2 m1 = (rem > 1) ? __ldg(perm + i + 1) : make_int2(m0.x, 0);
        int2 m2 = (rem > 2) ? __ldg(perm + i + 2) : make_int2(m0.x, 0);
        int2 m3 = (rem > 3) ? __ldg(perm + i + 3) : make_int2(m0.x, 0);
        uint2 r0 = __ldg((const uint2*)(H + (size_t)m0.x * D) + lane);
        uint2 r1 = __ldg((const uint2*)(H + (size_t)m1.x * D) + lane);
        uint2 r2 = __ldg((const uint2*)(H + (size_t)m2.x * D) + lane);
        uint2 r3 = __ldg((const uint2*)(H + (size_t)m3.x * D) + lane);
        float c0 = __int_as_float(m0.y);
        float c1 = __int_as_float(m1.y);
        float c2 = __int_as_float(m2.y);
        float c3 = __int_as_float(m3.y);
        float2 a00 = __half22float2(*(__half2*)&r0.x);
        float2 a01 = __half22float2(*(__half2*)&r0.y);
        float2 a10 = __half22float2(*(__half2*)&r1.x);
        float2 a11 = __half22float2(*(__half2*)&r1.y);
        float2 a20 = __half22float2(*(__half2*)&r2.x);
        float2 a21 = __half22float2(*(__half2*)&r2.y);
        float2 a30 = __half22float2(*(__half2*)&r3.x);
        float2 a31 = __half22float2(*(__half2*)&r3.y);
        acc.x = fmaf(c0, a00.x, fmaf(c1, a10.x, fmaf(c2, a20.x, fmaf(c3, a30.x, acc.x))));
        acc.y = fmaf(c0, a00.y, fmaf(c1, a10.y, fmaf(c2, a20.y, fmaf(c3, a30.y, acc.y))));
        acc.z = fmaf(c0, a01.x, fmaf(c1, a11.x, fmaf(c2, a21.x, fmaf(c3, a31.x, acc.z))));
        acc.w = fmaf(c0, a01.y, fmaf(c1, a11.y, fmaf(c2, a21.y, fmaf(c3, a31.y, acc.w))));
    }
    float4 o = make_float4(fmaxf(acc.x, 0.f), fmaxf(acc.y, 0.f),
                           fmaxf(acc.z, 0.f), fmaxf(acc.w, 0.f));
    *(float4*)(out + (size_t)row * D + lane * 4) = o;
}

extern "C" void kernel_launch(void* const* d_in, const int* in_sizes, int n_in,
                              void* d_out, int out_size) {
    const float* h_word  = (const float*)d_in[0];
    const float* h_topic = (const float*)d_in[1];
    const float* W_ww = (const float*)d_in[3];
    const float* b_ww = (const float*)d_in[4];
    const float* W_wt = (const float*)d_in[5];
    const float* b_wt = (const float*)d_in[6];
    const float* W_wd = (const float*)d_in[7];
    const float* b_wd = (const float*)d_in[8];
    const float* W_td = (const float*)d_in[9];
    const float* b_td = (const float*)d_in[10];
    const float* W_tt = (const float*)d_in[11];
    const float* b_tt = (const float*)d_in[12];
    const int*   src_ww = (const int*)d_in[13];
    const int*   dst_ww = (const int*)d_in[14];
    const float* ew_ww  = (const float*)d_in[15];
    const int*   src_wt = (const int*)d_in[16];
    const int*   dst_wt = (const int*)d_in[17];
    const float* ew_wt  = (const float*)d_in[18];
    const int*   src_wd = (const int*)d_in[19];
    const int*   dst_wd = (const int*)d_in[20];
    const float* ew_wd  = (const float*)d_in[21];
    const int*   src_td = (const int*)d_in[22];
    const int*   dst_td = (const int*)d_in[23];
    const float* ew_td  = (const float*)d_in[24];
    const int*   src_tt = (const int*)d_in[25];
    const int*   dst_tt = (const int*)d_in[26];
    const float* ew_tt  = (const float*)d_in[27];

    const int E_ww = in_sizes[13];
    const int E_wt = in_sizes[16];
    const int E_wd = in_sizes[19];
    const int E_td = in_sizes[22];
    const int E_tt = in_sizes[25];

    float* out = (float*)d_out;

    __half* H;
    float* rcnt;
    int *cntbuf, *offs, *cursor;
    int2 *perm, *rowdesc;
    cudaGetSymbolAddress((void**)&H, g_h);
    cudaGetSymbolAddress((void**)&cntbuf, g_cntbuf);
    cudaGetSymbolAddress((void**)&offs, g_offs);
    cudaGetSymbolAddress((void**)&cursor, g_cursor);
    cudaGetSymbolAddress((void**)&rcnt, g_rcnt);
    cudaGetSymbolAddress((void**)&perm, g_perm);
    cudaGetSymbolAddress((void**)&rowdesc, g_rowdesc);
    int* cnt = cntbuf;
    int* bsumZ = cntbuf + NV;

    const int VB_WW = 0,        VS_WW = 1;
    const int VB_WT = NW,       VS_WT = 2;
    const int VB_TT = NW + 1,   VS_TT = 2;
    const int VB_WD = NW + 2 * NT,     VS_WD = 2;
    const int VB_TD = NW + 2 * NT + 1, VS_TD = 2;

    // fork/join resources (leaked on purpose; ~2 calls total, capture-safe)
    cudaStream_t s2;
    cudaEvent_t evFork, evJoin;
    cudaStreamCreateWithFlags(&s2, cudaStreamNonBlocking);
    cudaEventCreateWithFlags(&evFork, cudaEventDisableTiming);
    cudaEventCreateWithFlags(&evJoin, cudaEventDisableTiming);

    cudaEventRecord(evFork, 0);
    cudaStreamWaitEvent(s2, evFork, 0);

    // ---- side stream: compose -> GEMM ----
    {
        const int csm = (128 * 129 + 128) * (int)sizeof(float);
        cudaFuncSetAttribute(compose1, cudaFuncAttributeMaxDynamicSharedMemorySize, csm);
        cudaFuncSetAttribute(compose2, cudaFuncAttributeMaxDynamicSharedMemorySize, csm);
        compose1<<<258, 128, csm, s2>>>(W_ww, W_wt, b_ww, b_wt, W_td, W_tt, b_td, b_tt);
        compose2<<<129, 128, csm, s2>>>(W_wd, b_wd);
        const int smem_bytes = 139264;
        cudaFuncSetAttribute(gemm_mma, cudaFuncAttributeMaxDynamicSharedMemorySize,
                             smem_bytes);
        gemm_mma<<<TILES_W + TILES_T, 256, smem_bytes, s2>>>(h_word, h_topic, H);
        cudaEventRecord(evJoin, s2);
    }

    // ---- main stream: CSR build chain ----
    cudaMemsetAsync(cntbuf, 0, (NV + SCAN_BLK) * sizeof(int), 0);
    {
        Cnt4Args ca;
        ca.dst4[0] = (const int4*)dst_ww; ca.vbase[0] = VB_WW; ca.vscale[0] = VS_WW;
        ca.dst4[1] = (const int4*)dst_wt; ca.vbase[1] = VB_WT; ca.vscale[1] = VS_WT;
        ca.dst4[2] = (const int4*)dst_tt; ca.vbase[2] = VB_TT; ca.vscale[2] = VS_TT;
        ca.dst4[3] = (const int4*)dst_wd; ca.vbase[3] = VB_WD; ca.vscale[3] = VS_WD;
        ca.dst4[4] = (const int4*)dst_td; ca.vbase[4] = VB_TD; ca.vscale[4] = VS_TD;
        ca.cum4[0] = 0;
        ca.cum4[1] = E_ww / 4;
        ca.cum4[2] = ca.cum4[1] + E_wt / 4;
        ca.cum4[3] = ca.cum4[2] + E_tt / 4;
        ca.cum4[4] = ca.cum4[3] + E_wd / 4;
        ca.cum4[5] = ca.cum4[4] + E_td / 4;
        count_all<<<(ca.cum4[5] + 255) / 256, 256>>>(ca, cnt);
    }
    scan_all<<<SCAN_BLK, 1024>>>(cnt, NV, offs, rcnt, cursor, bsumZ);
    rowdesc_kernel<<<(NROW + 255) / 256, 256>>>(offs, cnt, rowdesc);
    {
        Fill4Args fa;
        fa.src4[0] = (const int4*)src_ww; fa.dst4[0] = (const int4*)dst_ww; fa.ew4[0] = (const float4*)ew_ww; fa.vbase[0] = VB_WW; fa.vscale[0] = VS_WW; fa.soff[0] = 0;
        fa.src4[1] = (const int4*)src_wt; fa.dst4[1] = (const int4*)dst_wt; fa.ew4[1] = (const float4*)ew_wt; fa.vbase[1] = VB_WT; fa.vscale[1] = VS_WT; fa.soff[1] = 0;
        fa.src4[2] = (const int4*)src_tt; fa.dst4[2] = (const int4*)dst_tt; fa.ew4[2] = (const float4*)ew_tt; fa.vbase[2] = VB_TT; fa.vscale[2] = VS_TT; fa.soff[2] = NW;
        fa.src4[3] = (const int4*)src_wd; fa.dst4[3] = (const int4*)dst_wd; fa.ew4[3] = (const float4*)ew_wd; fa.vbase[3] = VB_WD; fa.vscale[3] = VS_WD; fa.soff[3] = 0;
        fa.src4[4] = (const int4*)src_td; fa.dst4[4] = (const int4*)dst_td; fa.ew4[4] = (const float4*)ew_td; fa.vbase[4] = VB_TD; fa.vscale[4] = VS_TD; fa.soff[4] = NW;
        fa.cum4[0] = 0;
        fa.cum4[1] = E_ww / 4;
        fa.cum4[2] = fa.cum4[1] + E_wt / 4;
        fa.cum4[3] = fa.cum4[2] + E_tt / 4;
        fa.cum4[4] = fa.cum4[3] + E_wd / 4;
        fa.cum4[5] = fa.cum4[4] + E_td / 4;
        fill_kernel<<<(fa.cum4[5] + 255) / 256, 256>>>(fa, rcnt, cursor, perm);
    }

    // join: gather needs both H (side) and CSR (main)
    cudaStreamWaitEvent(0, evJoin, 0);
    gather_kernel<<<(NROW * 32 + 255) / 256, 256>>>(perm, rowdesc, H, out);
}